// round 3
// baseline (speedup 1.0000x reference)
#include <cuda_runtime.h>
#include <cstdint>

#define BB 4
#define TT 4096
#define DM 1024
#define DH 64
#define CHT 8   // KV tiles (of 64) per attention work unit

// scratch (allocation-free rule: __device__ globals)
__device__ float g_q[BB * TT * DH];
__device__ float g_k[BB * TT * DH];
__device__ float g_v[BB * TT * DH];
// split-KV partials: [b][rt][chunk][i(64)][h(64)], l: [b][rt][chunk][i]
__device__ float g_po[BB * 64 * 8 * 64 * 64];
__device__ float g_pl[BB * 64 * 8 * 64];

// ---------------------------------------------------------------------------
// packed f32x2 helpers (sm_103a FFMA2 — only reachable via PTX)
// ---------------------------------------------------------------------------
__device__ __forceinline__ unsigned long long pack2(float lo, float hi) {
    unsigned long long r;
    asm("mov.b64 %0, {%1, %2};" : "=l"(r) : "f"(lo), "f"(hi));
    return r;
}
__device__ __forceinline__ void unpack2(unsigned long long v, float& lo, float& hi) {
    asm("mov.b64 {%0, %1}, %2;" : "=f"(lo), "=f"(hi) : "l"(v));
}
__device__ __forceinline__ void ffma2(unsigned long long& d,
                                      unsigned long long a,
                                      unsigned long long b) {
    asm("fma.rn.f32x2 %0, %1, %2, %0;" : "+l"(d) : "l"(a), "l"(b));
}

// ---------------------------------------------------------------------------
// QKV projection: out[m, h] = sum_d x[m, d] * W[h, d]
// M=16384, N=64, K=1024. BM=64, BN=64, BK=32, 256 thr, 4x4 micro (row-pairs),
// double-buffered smem with register-staged global loads.
// ---------------------------------------------------------------------------
__global__ void __launch_bounds__(256) proj_kernel(
    const float* __restrict__ x,
    const float* __restrict__ Wq,
    const float* __restrict__ Wk,
    const float* __restrict__ Wv)
{
    __shared__ float As[2][32][68];  // [buf][k][m]
    __shared__ float Bs[2][32][68];  // [buf][k][n]

    const float* W;
    float* out;
    if (blockIdx.y == 0)      { W = Wq; out = g_q; }
    else if (blockIdx.y == 1) { W = Wk; out = g_k; }
    else                      { W = Wv; out = g_v; }

    const int m0  = blockIdx.x * 64;
    const int tid = threadIdx.x;
    const int tx  = tid & 15;   // cols 4tx..4tx+3
    const int ty  = tid >> 4;   // rows 4ty..4ty+3

    // load indices: 512 float4 per tile (A and B each), 2 per thread
    const int lrow0 = (tid      ) >> 3;          // 0..31
    const int lrow1 = (tid + 256) >> 3;          // 32..63
    const int lc4   = (tid & 7) * 4;

    float4 ra[2], rb[2];

    // prologue: tile k0 = 0
    ra[0] = *(const float4*)(x + (size_t)(m0 + lrow0) * DM + lc4);
    ra[1] = *(const float4*)(x + (size_t)(m0 + lrow1) * DM + lc4);
    rb[0] = *(const float4*)(W + (size_t)lrow0 * DM + lc4);
    rb[1] = *(const float4*)(W + (size_t)lrow1 * DM + lc4);
    #pragma unroll
    for (int u = 0; u < 2; u++) {
        const int row = (u == 0) ? lrow0 : lrow1;
        float4 a = ra[u], b = rb[u];
        As[0][lc4 + 0][row] = a.x; As[0][lc4 + 1][row] = a.y;
        As[0][lc4 + 2][row] = a.z; As[0][lc4 + 3][row] = a.w;
        Bs[0][lc4 + 0][row] = b.x; Bs[0][lc4 + 1][row] = b.y;
        Bs[0][lc4 + 2][row] = b.z; Bs[0][lc4 + 3][row] = b.w;
    }
    __syncthreads();

    unsigned long long acc[2][4];
    #pragma unroll
    for (int rp = 0; rp < 2; rp++)
        #pragma unroll
        for (int c = 0; c < 4; c++) acc[rp][c] = 0ull;

    int cur = 0;
    for (int it = 0; it < 32; it++) {
        const int k0n = (it + 1) * 32;
        if (it < 31) {
            ra[0] = *(const float4*)(x + (size_t)(m0 + lrow0) * DM + k0n + lc4);
            ra[1] = *(const float4*)(x + (size_t)(m0 + lrow1) * DM + k0n + lc4);
            rb[0] = *(const float4*)(W + (size_t)lrow0 * DM + k0n + lc4);
            rb[1] = *(const float4*)(W + (size_t)lrow1 * DM + k0n + lc4);
        }
        #pragma unroll
        for (int kk = 0; kk < 32; kk++) {
            ulonglong2 ap = *(const ulonglong2*)(&As[cur][kk][4 * ty]);
            float4 b4 = *(const float4*)(&Bs[cur][kk][4 * tx]);
            unsigned long long bsp[4];
            bsp[0] = pack2(b4.x, b4.x); bsp[1] = pack2(b4.y, b4.y);
            bsp[2] = pack2(b4.z, b4.z); bsp[3] = pack2(b4.w, b4.w);
            #pragma unroll
            for (int c = 0; c < 4; c++) {
                ffma2(acc[0][c], ap.x, bsp[c]);
                ffma2(acc[1][c], ap.y, bsp[c]);
            }
        }
        if (it < 31) {
            const int nxt = cur ^ 1;
            #pragma unroll
            for (int u = 0; u < 2; u++) {
                const int row = (u == 0) ? lrow0 : lrow1;
                float4 a = ra[u], b = rb[u];
                As[nxt][lc4 + 0][row] = a.x; As[nxt][lc4 + 1][row] = a.y;
                As[nxt][lc4 + 2][row] = a.z; As[nxt][lc4 + 3][row] = a.w;
                Bs[nxt][lc4 + 0][row] = b.x; Bs[nxt][lc4 + 1][row] = b.y;
                Bs[nxt][lc4 + 2][row] = b.z; Bs[nxt][lc4 + 3][row] = b.w;
            }
        }
        __syncthreads();
        cur ^= 1;
    }

    // epilogue: unpack row-pairs, store 4 rows x float4
    float o[4][4];
    #pragma unroll
    for (int rp = 0; rp < 2; rp++)
        #pragma unroll
        for (int c = 0; c < 4; c++)
            unpack2(acc[rp][c], o[2 * rp][c], o[2 * rp + 1][c]);
    #pragma unroll
    for (int r = 0; r < 4; r++)
        *(float4*)(out + (size_t)(m0 + 4 * ty + r) * DH + 4 * tx) =
            make_float4(o[r][0], o[r][1], o[r][2], o[r][3]);
}

// ---------------------------------------------------------------------------
// Split-KV flash attention partial (no max-tracking: scores bounded, exp safe).
// block = (rt, chunk, b); KV tiles ct in [chunk*CHT, min(rt, ...)].
// ---------------------------------------------------------------------------
#define SROW 68
#define SMEM_FLOATS (4 * 64 * SROW + 32)
#define SMEM_BYTES  (SMEM_FLOATS * 4)

__global__ void __launch_bounds__(256) attn_part_kernel(
    const float* __restrict__ rel_emb)
{
    const int rt    = blockIdx.x;
    const int chunk = blockIdx.y;
    const int b     = blockIdx.z;
    const int ct0   = chunk * CHT;
    if (ct0 > rt) return;
    const int ct1 = min(rt, ct0 + CHT - 1);

    extern __shared__ float sm[];
    float* Qs   = sm;
    float* Ks   = sm + 64 * SROW;
    float* Vs   = sm + 2 * 64 * SROW;
    float* Ps   = sm + 3 * 64 * SROW;
    float* sRel = sm + 4 * 64 * SROW;

    const int tid = threadIdx.x;
    const int tx  = tid & 15;
    const int ty  = tid >> 4;
    const int i0  = rt * 64;

    if (tid < 17) sRel[tid] = rel_emb[tid];

    // load Q tile transposed: Qs[h][i]
    {
        const int i  = tid >> 2;
        const int hb = (tid & 3) * 4;
        const float* qp = g_q + (size_t)(b * TT + i0 + i) * DH;
        #pragma unroll
        for (int q = 0; q < 4; q++) {
            const int h = hb + 16 * q;
            float4 v = *(const float4*)(qp + h);
            Qs[(h + 0) * SROW + i] = v.x;
            Qs[(h + 1) * SROW + i] = v.y;
            Qs[(h + 2) * SROW + i] = v.z;
            Qs[(h + 3) * SROW + i] = v.w;
        }
    }

    unsigned long long op[2][4];
    #pragma unroll
    for (int rp = 0; rp < 2; rp++)
        #pragma unroll
        for (int c = 0; c < 4; c++) op[rp][c] = 0ull;
    float l_loc[4] = {0.f, 0.f, 0.f, 0.f};

    for (int ct = ct0; ct <= ct1; ct++) {
        const int j0 = ct * 64;
        __syncthreads();   // prev PV reads of Ps/Vs done
        {
            const int j  = tid >> 2;
            const int hb = (tid & 3) * 4;
            const float* kp = g_k + (size_t)(b * TT + j0 + j) * DH;
            const float* vp = g_v + (size_t)(b * TT + j0 + j) * DH;
            #pragma unroll
            for (int q = 0; q < 4; q++) {
                const int h = hb + 16 * q;
                float4 kv = *(const float4*)(kp + h);
                Ks[(h + 0) * SROW + j] = kv.x;
                Ks[(h + 1) * SROW + j] = kv.y;
                Ks[(h + 2) * SROW + j] = kv.z;
                Ks[(h + 3) * SROW + j] = kv.w;
                float4 vv = *(const float4*)(vp + h);
                *(float4*)(&Vs[j * SROW + h]) = vv;
            }
        }
        __syncthreads();

        // S = Q K^T (row-paired f32x2)
        unsigned long long sp[2][4];
        #pragma unroll
        for (int rp = 0; rp < 2; rp++)
            #pragma unroll
            for (int c = 0; c < 4; c++) sp[rp][c] = 0ull;
        #pragma unroll 16
        for (int kk = 0; kk < 64; kk++) {
            ulonglong2 ap = *(const ulonglong2*)(&Qs[kk * SROW + 4 * ty]);
            float4 b4 = *(const float4*)(&Ks[kk * SROW + 4 * tx]);
            unsigned long long bsp[4];
            bsp[0] = pack2(b4.x, b4.x); bsp[1] = pack2(b4.y, b4.y);
            bsp[2] = pack2(b4.z, b4.z); bsp[3] = pack2(b4.w, b4.w);
            #pragma unroll
            for (int c = 0; c < 4; c++) {
                ffma2(sp[0][c], ap.x, bsp[c]);
                ffma2(sp[1][c], ap.y, bsp[c]);
            }
        }

        // unpack, scale + bias (+ mask), exp (no max subtraction)
        float s[4][4];
        #pragma unroll
        for (int c = 0; c < 4; c++) {
            unpack2(sp[0][c], s[0][c], s[1][c]);
            unpack2(sp[1][c], s[2][c], s[3][c]);
        }
        const float b0 = sRel[0];
        if (ct + 1 < rt) {
            #pragma unroll
            for (int r = 0; r < 4; r++)
                #pragma unroll
                for (int c = 0; c < 4; c++) {
                    const float p = __expf(s[r][c] * 0.125f + b0);
                    s[r][c] = p;
                    l_loc[r] += p;
                }
        } else {
            #pragma unroll
            for (int r = 0; r < 4; r++)
                #pragma unroll
                for (int c = 0; c < 4; c++) {
                    const int d = (j0 + 4 * tx + c) - (i0 + 4 * ty + r);
                    float p = 0.f;
                    if (d <= 0)
                        p = __expf(s[r][c] * 0.125f + sRel[(d < -8 ? -8 : d) + 8]);
                    s[r][c] = p;
                    l_loc[r] += p;
                }
        }

        // stage P transposed: Ps[j][i]
        #pragma unroll
        for (int c = 0; c < 4; c++)
            *(float4*)(&Ps[(4 * tx + c) * SROW + 4 * ty]) =
                make_float4(s[0][c], s[1][c], s[2][c], s[3][c]);
        __syncthreads();

        // O += P V (row-paired f32x2)
        #pragma unroll 16
        for (int jj = 0; jj < 64; jj++) {
            ulonglong2 ap = *(const ulonglong2*)(&Ps[jj * SROW + 4 * ty]);
            float4 b4 = *(const float4*)(&Vs[jj * SROW + 4 * tx]);
            unsigned long long bsp[4];
            bsp[0] = pack2(b4.x, b4.x); bsp[1] = pack2(b4.y, b4.y);
            bsp[2] = pack2(b4.z, b4.z); bsp[3] = pack2(b4.w, b4.w);
            #pragma unroll
            for (int c = 0; c < 4; c++) {
                ffma2(op[0][c], ap.x, bsp[c]);
                ffma2(op[1][c], ap.y, bsp[c]);
            }
        }
    }

    // reduce row sums across the 16-thread col-groups (once per kernel)
    #pragma unroll
    for (int r = 0; r < 4; r++) {
        float rs = l_loc[r];
        rs += __shfl_xor_sync(0xffffffffu, rs, 1);
        rs += __shfl_xor_sync(0xffffffffu, rs, 2);
        rs += __shfl_xor_sync(0xffffffffu, rs, 4);
        rs += __shfl_xor_sync(0xffffffffu, rs, 8);
        l_loc[r] = rs;
    }

    // write partials (unnormalized O, l)
    const size_t unit = ((size_t)(b * 64 + rt) * 8 + chunk);
    float* po = g_po + unit * 64 * 64;
    float o[4][4];
    #pragma unroll
    for (int rp = 0; rp < 2; rp++)
        #pragma unroll
        for (int c = 0; c < 4; c++)
            unpack2(op[rp][c], o[2 * rp][c], o[2 * rp + 1][c]);
    #pragma unroll
    for (int r = 0; r < 4; r++) {
        *(float4*)(po + (size_t)(4 * ty + r) * 64 + 4 * tx) =
            make_float4(o[r][0], o[r][1], o[r][2], o[r][3]);
        if (tx == 0) g_pl[unit * 64 + 4 * ty + r] = l_loc[r];
    }
}

// ---------------------------------------------------------------------------
// Combine partials: out = (sum_p O_p) / (sum_p l_p)
// ---------------------------------------------------------------------------
__global__ void __launch_bounds__(256) combine_kernel(float* __restrict__ out)
{
    const int rt  = blockIdx.x;
    const int b   = blockIdx.y;
    const int nch = rt / CHT + 1;
    const size_t base = ((size_t)(b * 64 + rt) * 8);

    __shared__ float sInvL[64];

    const int tid = threadIdx.x;
    if (tid < 64) {
        float L = 0.f;
        for (int p = 0; p < nch; p++)
            L += g_pl[(base + p) * 64 + tid];
        sInvL[tid] = 1.0f / L;
    }
    __syncthreads();

    const int r  = tid >> 2;
    const int h0 = (tid & 3) * 16;
    float acc[16] = {};
    for (int p = 0; p < nch; p++) {
        const float* po = g_po + ((base + p) * 64 + r) * 64 + h0;
        #pragma unroll
        for (int u = 0; u < 16; u += 4) {
            float4 v = *(const float4*)(po + u);
            acc[u + 0] += v.x; acc[u + 1] += v.y;
            acc[u + 2] += v.z; acc[u + 3] += v.w;
        }
    }
    const float inv = sInvL[r];
    float* opnt = out + (size_t)(b * TT + rt * 64 + r) * DH + h0;
    #pragma unroll
    for (int u = 0; u < 16; u += 4)
        *(float4*)(opnt + u) = make_float4(acc[u] * inv, acc[u + 1] * inv,
                                           acc[u + 2] * inv, acc[u + 3] * inv);
}

extern "C" void kernel_launch(void* const* d_in, const int* in_sizes, int n_in,
                              void* d_out, int out_size)
{
    const float* x   = (const float*)d_in[0];
    const float* Wq  = (const float*)d_in[1];
    const float* Wk  = (const float*)d_in[2];
    const float* Wv  = (const float*)d_in[3];
    const float* rel = (const float*)d_in[4];
    float* out = (float*)d_out;

    dim3 pgrid(BB * TT / 64, 3);
    proj_kernel<<<pgrid, 256>>>(x, Wq, Wk, Wv);

    cudaFuncSetAttribute(attn_part_kernel,
                         cudaFuncAttributeMaxDynamicSharedMemorySize, SMEM_BYTES);
    dim3 agrid(TT / 64, 8, BB);
    attn_part_kernel<<<agrid, 256, SMEM_BYTES>>>(rel);

    dim3 cgrid(TT / 64, BB);
    combine_kernel<<<cgrid, 256>>>(out);
}

// round 4
// speedup vs baseline: 1.1380x; 1.1380x over previous
#include <cuda_runtime.h>
#include <cstdint>

#define BB 4
#define TT 4096
#define DM 1024
#define DH 64

// scratch (allocation-free rule: __device__ globals)
__device__ float g_q[BB * TT * DH];
__device__ float g_k[BB * TT * DH];
__device__ float g_v[BB * TT * DH];
// split-KV partials: unit = (b, rt(32 of 128 rows), chunk(8)); O:128x64, l:128
__device__ float g_po[BB * 32 * 8 * 128 * 64];
__device__ float g_pl[BB * 32 * 8 * 128];

// ---------------------------------------------------------------------------
// packed f32x2 helpers (sm_103a FFMA2 — only reachable via PTX)
// ---------------------------------------------------------------------------
__device__ __forceinline__ unsigned long long splat2(float v) {
    unsigned long long r;
    asm("mov.b64 %0, {%1, %1};" : "=l"(r) : "f"(v));
    return r;
}
__device__ __forceinline__ void unpack2(unsigned long long v, float& lo, float& hi) {
    asm("mov.b64 {%0, %1}, %2;" : "=f"(lo), "=f"(hi) : "l"(v));
}
__device__ __forceinline__ void ffma2(unsigned long long& d,
                                      unsigned long long a,
                                      unsigned long long b) {
    asm("fma.rn.f32x2 %0, %1, %2, %0;" : "+l"(d) : "l"(a), "l"(b));
}

// 32 FFMA2 for an 8x8 tile: a = 4 row-pairs, bs = 8 col splats
#define TILE_FFMA2(acc, a01, a23, bs)                                   \
    {                                                                   \
        _Pragma("unroll")                                               \
        for (int _c = 0; _c < 8; _c++) {                                \
            ffma2(acc[0][_c], a01.x, bs[_c]);                           \
            ffma2(acc[1][_c], a01.y, bs[_c]);                           \
            ffma2(acc[2][_c], a23.x, bs[_c]);                           \
            ffma2(acc[3][_c], a23.y, bs[_c]);                           \
        }                                                               \
    }

#define SPLAT8(bs, b0, b1)                                              \
    unsigned long long bs[8];                                           \
    bs[0] = splat2(b0.x); bs[1] = splat2(b0.y);                         \
    bs[2] = splat2(b0.z); bs[3] = splat2(b0.w);                         \
    bs[4] = splat2(b1.x); bs[5] = splat2(b1.y);                         \
    bs[6] = splat2(b1.z); bs[7] = splat2(b1.w);

// ---------------------------------------------------------------------------
// QKV projection: out[m, h] = sum_d x[m, d] * W[h, d]
// M=16384, N=64, K=1024. BM=128, BN=64, BK=32, 128 threads, 8x8 micro tile
// (row-paired FFMA2), double-buffered smem, register-staged global loads.
// ---------------------------------------------------------------------------
__global__ void __launch_bounds__(128) proj_kernel(
    const float* __restrict__ x,
    const float* __restrict__ Wq,
    const float* __restrict__ Wk,
    const float* __restrict__ Wv)
{
    __shared__ float As[2][32][132];  // [buf][k][m]
    __shared__ float Bs[2][32][68];   // [buf][k][n]

    const float* W;
    float* out;
    if (blockIdx.y == 0)      { W = Wq; out = g_q; }
    else if (blockIdx.y == 1) { W = Wk; out = g_k; }
    else                      { W = Wv; out = g_v; }

    const int m0  = blockIdx.x * 128;
    const int tid = threadIdx.x;
    const int tx  = tid & 7;    // cols 8tx..8tx+7
    const int ty  = tid >> 3;   // rows 8ty..8ty+7 (compute) / load row base
    const int c4  = tx * 4;     // load col offset

    // prologue: tile k0 = 0 straight into buffer 0
    #pragma unroll
    for (int it = 0; it < 8; it++) {
        const int row = ty + 16 * it;        // 0..127
        float4 a = *(const float4*)(x + (size_t)(m0 + row) * DM + c4);
        As[0][c4 + 0][row] = a.x; As[0][c4 + 1][row] = a.y;
        As[0][c4 + 2][row] = a.z; As[0][c4 + 3][row] = a.w;
    }
    #pragma unroll
    for (int it = 0; it < 4; it++) {
        const int row = ty + 16 * it;        // 0..63
        float4 w = *(const float4*)(W + (size_t)row * DM + c4);
        Bs[0][c4 + 0][row] = w.x; Bs[0][c4 + 1][row] = w.y;
        Bs[0][c4 + 2][row] = w.z; Bs[0][c4 + 3][row] = w.w;
    }
    __syncthreads();

    unsigned long long acc[4][8];
    #pragma unroll
    for (int p = 0; p < 4; p++)
        #pragma unroll
        for (int c = 0; c < 8; c++) acc[p][c] = 0ull;

    float4 ra[8], rb[4];
    int cur = 0;
    for (int t = 0; t < 32; t++) {
        if (t < 31) {
            const int k0 = (t + 1) * 32;
            #pragma unroll
            for (int it = 0; it < 8; it++)
                ra[it] = *(const float4*)(x + (size_t)(m0 + ty + 16 * it) * DM + k0 + c4);
            #pragma unroll
            for (int it = 0; it < 4; it++)
                rb[it] = *(const float4*)(W + (size_t)(ty + 16 * it) * DM + k0 + c4);
        }
        #pragma unroll 8
        for (int kk = 0; kk < 32; kk++) {
            ulonglong2 a01 = *(const ulonglong2*)(&As[cur][kk][8 * ty]);
            ulonglong2 a23 = *(const ulonglong2*)(&As[cur][kk][8 * ty + 4]);
            float4 b0 = *(const float4*)(&Bs[cur][kk][8 * tx]);
            float4 b1 = *(const float4*)(&Bs[cur][kk][8 * tx + 4]);
            SPLAT8(bs, b0, b1);
            TILE_FFMA2(acc, a01, a23, bs);
        }
        if (t < 31) {
            const int nxt = cur ^ 1;
            #pragma unroll
            for (int it = 0; it < 8; it++) {
                const int row = ty + 16 * it;
                As[nxt][c4 + 0][row] = ra[it].x; As[nxt][c4 + 1][row] = ra[it].y;
                As[nxt][c4 + 2][row] = ra[it].z; As[nxt][c4 + 3][row] = ra[it].w;
            }
            #pragma unroll
            for (int it = 0; it < 4; it++) {
                const int row = ty + 16 * it;
                Bs[nxt][c4 + 0][row] = rb[it].x; Bs[nxt][c4 + 1][row] = rb[it].y;
                Bs[nxt][c4 + 2][row] = rb[it].z; Bs[nxt][c4 + 3][row] = rb[it].w;
            }
        }
        __syncthreads();
        cur ^= 1;
    }

    // epilogue: unpack row pairs (rows 8ty+2p, 8ty+2p+1), store float4 x2 per row
    #pragma unroll
    for (int p = 0; p < 4; p++) {
        float lo[8], hi[8];
        #pragma unroll
        for (int c = 0; c < 8; c++) unpack2(acc[p][c], lo[c], hi[c]);
        float* o0 = out + (size_t)(m0 + 8 * ty + 2 * p) * DH + 8 * tx;
        float* o1 = o0 + DH;
        *(float4*)(o0)     = make_float4(lo[0], lo[1], lo[2], lo[3]);
        *(float4*)(o0 + 4) = make_float4(lo[4], lo[5], lo[6], lo[7]);
        *(float4*)(o1)     = make_float4(hi[0], hi[1], hi[2], hi[3]);
        *(float4*)(o1 + 4) = make_float4(hi[4], hi[5], hi[6], hi[7]);
    }
}

// ---------------------------------------------------------------------------
// Split-KV flash attention partial. Br=128, Bc=64, 128 threads, 8x8 tiles.
// block = (rt, chunk, b); KV tiles ct (64 cols) in [8*chunk, min(2rt+1, ...)].
// No max-tracking (scores bounded); writes unnormalized O + l to scratch.
// ---------------------------------------------------------------------------
#define SQ 132
#define SK 68
#define ASMEM_FLOATS (2 * 64 * SQ + 2 * 64 * SK + 32)
#define ASMEM_BYTES  (ASMEM_FLOATS * 4)

__global__ void __launch_bounds__(128) attn_part_kernel(
    const float* __restrict__ rel_emb)
{
    const int rt    = blockIdx.x;       // 0..31, rows [128rt, 128rt+128)
    const int chunk = blockIdx.y;       // 0..7
    const int b     = blockIdx.z;
    const int ct0   = chunk * 8;
    const int ctmax = 2 * rt + 1;
    if (ct0 > ctmax) return;
    const int ct1 = min(ctmax, ct0 + 7);

    extern __shared__ float sm[];
    float* Qs   = sm;                   // [h(64)][i(128)] stride SQ
    float* Ks   = sm + 64 * SQ;         // [h(64)][j(64)]  stride SK
    float* Vs   = Ks + 64 * SK;         // [j(64)][h(64)]  stride SK
    float* Ps   = Vs + 64 * SK;         // [j(64)][i(128)] stride SQ
    float* sRel = Ps + 64 * SQ;

    const int tid = threadIdx.x;
    const int tx  = tid & 7;            // col group: 8tx..8tx+7
    const int ty  = tid >> 3;           // row group: 8ty..8ty+7
    const int i0  = rt * 128;

    if (tid < 17) sRel[tid] = rel_emb[tid];

    // load Q tile transposed: Qs[h][i], 128 i x 64 h
    #pragma unroll
    for (int it = 0; it < 16; it++) {
        const int idx = tid + 128 * it;
        const int i   = idx >> 4;          // 0..127
        const int hb  = (idx & 15) * 4;
        float4 v = *(const float4*)(g_q + (size_t)(b * TT + i0 + i) * DH + hb);
        Qs[(hb + 0) * SQ + i] = v.x;
        Qs[(hb + 1) * SQ + i] = v.y;
        Qs[(hb + 2) * SQ + i] = v.z;
        Qs[(hb + 3) * SQ + i] = v.w;
    }

    unsigned long long oacc[4][8];
    #pragma unroll
    for (int p = 0; p < 4; p++)
        #pragma unroll
        for (int c = 0; c < 8; c++) oacc[p][c] = 0ull;
    float l_loc[8] = {0.f, 0.f, 0.f, 0.f, 0.f, 0.f, 0.f, 0.f};

    for (int ct = ct0; ct <= ct1; ct++) {
        const int j0 = ct * 64;
        __syncthreads();   // prev PV reads of Ks/Vs/Ps done
        // load K transposed (Ks[h][j]) and V natural (Vs[j][h])
        #pragma unroll
        for (int it = 0; it < 8; it++) {
            const int idx = tid + 128 * it;
            const int j   = idx >> 4;        // 0..63
            const int hb  = (idx & 15) * 4;
            float4 kv = *(const float4*)(g_k + (size_t)(b * TT + j0 + j) * DH + hb);
            Ks[(hb + 0) * SK + j] = kv.x;
            Ks[(hb + 1) * SK + j] = kv.y;
            Ks[(hb + 2) * SK + j] = kv.z;
            Ks[(hb + 3) * SK + j] = kv.w;
            float4 vv = *(const float4*)(g_v + (size_t)(b * TT + j0 + j) * DH + hb);
            *(float4*)(&Vs[j * SK + hb]) = vv;
        }
        __syncthreads();

        // S = Q K^T (8x8 per thread, row-paired FFMA2)
        unsigned long long sacc[4][8];
        #pragma unroll
        for (int p = 0; p < 4; p++)
            #pragma unroll
            for (int c = 0; c < 8; c++) sacc[p][c] = 0ull;
        #pragma unroll 8
        for (int kk = 0; kk < 64; kk++) {
            ulonglong2 a01 = *(const ulonglong2*)(&Qs[kk * SQ + 8 * ty]);
            ulonglong2 a23 = *(const ulonglong2*)(&Qs[kk * SQ + 8 * ty + 4]);
            float4 b0 = *(const float4*)(&Ks[kk * SK + 8 * tx]);
            float4 b1 = *(const float4*)(&Ks[kk * SK + 8 * tx + 4]);
            SPLAT8(bs, b0, b1);
            TILE_FFMA2(sacc, a01, a23, bs);
        }

        // bias + exp (+ mask near diagonal), accumulate l, stage P transposed
        const float b0v = sRel[0];
        if (ct <= 2 * rt - 2) {
            // far tile: j - i <= -9 everywhere -> uniform rel_emb[0], no mask
            #pragma unroll
            for (int c = 0; c < 8; c++) {
                float e[8];
                #pragma unroll
                for (int p = 0; p < 4; p++) {
                    float lo, hi;
                    unpack2(sacc[p][c], lo, hi);
                    e[2 * p]     = __expf(lo * 0.125f + b0v);
                    e[2 * p + 1] = __expf(hi * 0.125f + b0v);
                }
                #pragma unroll
                for (int r = 0; r < 8; r++) l_loc[r] += e[r];
                float* pp = &Ps[(8 * tx + c) * SQ + 8 * ty];
                *(float4*)(pp)     = make_float4(e[0], e[1], e[2], e[3]);
                *(float4*)(pp + 4) = make_float4(e[4], e[5], e[6], e[7]);
            }
        } else {
            const int jb = j0 + 8 * tx;
            const int ib = i0 + 8 * ty;
            #pragma unroll
            for (int c = 0; c < 8; c++) {
                const int j = jb + c;
                float e[8];
                #pragma unroll
                for (int p = 0; p < 4; p++) {
                    float lo, hi;
                    unpack2(sacc[p][c], lo, hi);
                    const int d0 = j - (ib + 2 * p);
                    const int d1 = d0 - 1;
                    e[2 * p]     = (d0 <= 0)
                        ? __expf(lo * 0.125f + sRel[(d0 < -8 ? -8 : d0) + 8]) : 0.f;
                    e[2 * p + 1] = (d1 <= 0)
                        ? __expf(hi * 0.125f + sRel[(d1 < -8 ? -8 : d1) + 8]) : 0.f;
                }
                #pragma unroll
                for (int r = 0; r < 8; r++) l_loc[r] += e[r];
                float* pp = &Ps[(8 * tx + c) * SQ + 8 * ty];
                *(float4*)(pp)     = make_float4(e[0], e[1], e[2], e[3]);
                *(float4*)(pp + 4) = make_float4(e[4], e[5], e[6], e[7]);
            }
        }
        __syncthreads();

        // O += P V (8x8 per thread, row-paired FFMA2)
        #pragma unroll 8
        for (int jj = 0; jj < 64; jj++) {
            ulonglong2 p01 = *(const ulonglong2*)(&Ps[jj * SQ + 8 * ty]);
            ulonglong2 p23 = *(const ulonglong2*)(&Ps[jj * SQ + 8 * ty + 4]);
            float4 v0 = *(const float4*)(&Vs[jj * SK + 8 * tx]);
            float4 v1 = *(const float4*)(&Vs[jj * SK + 8 * tx + 4]);
            SPLAT8(vs, v0, v1);
            TILE_FFMA2(oacc, p01, p23, vs);
        }
    }

    // reduce row sums across the 8 col-group lanes (once per kernel)
    #pragma unroll
    for (int r = 0; r < 8; r++) {
        float rs = l_loc[r];
        rs += __shfl_xor_sync(0xffffffffu, rs, 1);
        rs += __shfl_xor_sync(0xffffffffu, rs, 2);
        rs += __shfl_xor_sync(0xffffffffu, rs, 4);
        l_loc[r] = rs;
    }

    // write partials (unnormalized O rows 8ty..8ty+7, cols 8tx..8tx+7; l)
    const size_t unit = ((size_t)(b * 32 + rt) * 8 + chunk);
    float* po = g_po + unit * 128 * 64;
    #pragma unroll
    for (int p = 0; p < 4; p++) {
        float lo[8], hi[8];
        #pragma unroll
        for (int c = 0; c < 8; c++) unpack2(oacc[p][c], lo[c], hi[c]);
        float* o0 = po + (size_t)(8 * ty + 2 * p) * DH + 8 * tx;
        float* o1 = o0 + DH;
        *(float4*)(o0)     = make_float4(lo[0], lo[1], lo[2], lo[3]);
        *(float4*)(o0 + 4) = make_float4(lo[4], lo[5], lo[6], lo[7]);
        *(float4*)(o1)     = make_float4(hi[0], hi[1], hi[2], hi[3]);
        *(float4*)(o1 + 4) = make_float4(hi[4], hi[5], hi[6], hi[7]);
    }
    if (tx == 0) {
        #pragma unroll
        for (int r = 0; r < 8; r++)
            g_pl[unit * 128 + 8 * ty + r] = l_loc[r];
    }
}

// ---------------------------------------------------------------------------
// Combine partials: out = (sum_p O_p) / (sum_p l_p).  Block = (rt, b), 128 rows.
// ---------------------------------------------------------------------------
__global__ void __launch_bounds__(256) combine_kernel(float* __restrict__ out)
{
    const int rt  = blockIdx.x;
    const int b   = blockIdx.y;
    const int nch = (2 * rt + 9) >> 3;   // ceil((2rt+2)/8)
    const size_t base = (size_t)(b * 32 + rt) * 8;

    __shared__ float sInvL[128];

    const int tid = threadIdx.x;
    if (tid < 128) {
        float L = 0.f;
        for (int p = 0; p < nch; p++)
            L += g_pl[(base + p) * 128 + tid];
        sInvL[tid] = 1.0f / L;
    }
    __syncthreads();

    const int r  = tid >> 1;            // 0..127
    const int h0 = (tid & 1) * 32;
    float acc[32] = {};
    for (int p = 0; p < nch; p++) {
        const float* po = g_po + ((base + p) * 128 + r) * 64 + h0;
        #pragma unroll
        for (int u = 0; u < 32; u += 4) {
            float4 v = *(const float4*)(po + u);
            acc[u + 0] += v.x; acc[u + 1] += v.y;
            acc[u + 2] += v.z; acc[u + 3] += v.w;
        }
    }
    const float inv = sInvL[r];
    float* op = out + (size_t)(b * TT + rt * 128 + r) * DH + h0;
    #pragma unroll
    for (int u = 0; u < 32; u += 4)
        *(float4*)(op + u) = make_float4(acc[u] * inv, acc[u + 1] * inv,
                                         acc[u + 2] * inv, acc[u + 3] * inv);
}

extern "C" void kernel_launch(void* const* d_in, const int* in_sizes, int n_in,
                              void* d_out, int out_size)
{
    const float* x   = (const float*)d_in[0];
    const float* Wq  = (const float*)d_in[1];
    const float* Wk  = (const float*)d_in[2];
    const float* Wv  = (const float*)d_in[3];
    const float* rel = (const float*)d_in[4];
    float* out = (float*)d_out;

    dim3 pgrid(BB * TT / 128, 3);
    proj_kernel<<<pgrid, 128>>>(x, Wq, Wk, Wv);

    cudaFuncSetAttribute(attn_part_kernel,
                         cudaFuncAttributeMaxDynamicSharedMemorySize, ASMEM_BYTES);
    dim3 agrid(32, 8, BB);
    attn_part_kernel<<<agrid, 128, ASMEM_BYTES>>>(rel);

    dim3 cgrid(32, BB);
    combine_kernel<<<cgrid, 256>>>(out);
}

// round 7
// speedup vs baseline: 1.4356x; 1.2615x over previous
#include <cuda_runtime.h>
#include <cuda_bf16.h>
#include <cstdint>

#define BB 4
#define TT 4096
#define DM 1024
#define DH 64

// scratch (allocation-free rule: __device__ globals)
__device__ float g_q[BB * TT * DH];
__device__ float g_k[BB * TT * DH];
__device__ float g_v[BB * TT * DH];
// split-KV partials: unit = (b, rt(32 of 128 rows), chunk(8)); O:128x64, l:128
__device__ float g_po[BB * 32 * 8 * 128 * 64];
__device__ float g_pl[BB * 32 * 8 * 128];
// bf16x3 split operands
__device__ __nv_bfloat16 g_xh[BB * TT * DM];
__device__ __nv_bfloat16 g_xl[BB * TT * DM];
__device__ __nv_bfloat16 g_wh[3 * DH * DM];
__device__ __nv_bfloat16 g_wl[3 * DH * DM];

// ===========================================================================
// base-ISA helpers: cp.async, ldmatrix, mma.sync (all legal on sm_103)
// ===========================================================================
__device__ __forceinline__ uint32_t smem_u32(const void* p) {
    uint32_t a;
    asm("{ .reg .u64 t; cvta.to.shared.u64 t, %1; cvt.u32.u64 %0, t; }"
        : "=r"(a) : "l"(p));
    return a;
}
__device__ __forceinline__ void cp16(uint32_t dst, const void* src) {
    asm volatile("cp.async.cg.shared.global [%0], [%1], 16;"
                 :: "r"(dst), "l"(src) : "memory");
}
#define CP_COMMIT() asm volatile("cp.async.commit_group;" ::: "memory")
#define CP_WAIT0()  asm volatile("cp.async.wait_group 0;" ::: "memory")

#define LDMX4(r, addr)                                                       \
    asm volatile("ldmatrix.sync.aligned.m8n8.x4.shared.b16 {%0,%1,%2,%3}, [%4];" \
        : "=r"((r)[0]), "=r"((r)[1]), "=r"((r)[2]), "=r"((r)[3]) : "r"(addr))

__device__ __forceinline__ void mma16816(float* d, const uint32_t* a,
                                         uint32_t b0, uint32_t b1) {
    asm volatile(
        "mma.sync.aligned.m16n8k16.row.col.f32.bf16.bf16.f32 "
        "{%0,%1,%2,%3}, {%4,%5,%6,%7}, {%8,%9}, {%0,%1,%2,%3};"
        : "+f"(d[0]), "+f"(d[1]), "+f"(d[2]), "+f"(d[3])
        : "r"(a[0]), "r"(a[1]), "r"(a[2]), "r"(a[3]), "r"(b0), "r"(b1));
}

// ===========================================================================
// convert kernels: fp32 -> (hi, lo) bf16
// ===========================================================================
__device__ __forceinline__ void split_store(float f, __nv_bfloat16& h, __nv_bfloat16& l) {
    h = __float2bfloat16(f);
    l = __float2bfloat16(f - __bfloat162float(h));
}
__global__ void __launch_bounds__(256) convert_x_kernel(const float* __restrict__ x)
{
    const int stride = gridDim.x * 256;
    for (int i4 = blockIdx.x * 256 + threadIdx.x; i4 < BB * TT * DM / 4; i4 += stride) {
        float4 f = *(const float4*)(x + (size_t)i4 * 4);
        __nv_bfloat16 h[4], l[4];
        split_store(f.x, h[0], l[0]); split_store(f.y, h[1], l[1]);
        split_store(f.z, h[2], l[2]); split_store(f.w, h[3], l[3]);
        *(uint2*)(g_xh + (size_t)i4 * 4) = *(uint2*)h;
        *(uint2*)(g_xl + (size_t)i4 * 4) = *(uint2*)l;
    }
}
__global__ void __launch_bounds__(256) convert_w_kernel(
    const float* __restrict__ Wq, const float* __restrict__ Wk,
    const float* __restrict__ Wv)
{
    const float* W = (blockIdx.y == 0) ? Wq : (blockIdx.y == 1) ? Wk : Wv;
    const size_t base = (size_t)blockIdx.y * DH * DM;
    const int i4 = blockIdx.x * 256 + threadIdx.x;   // 16384 float4 per W
    float4 f = *(const float4*)(W + (size_t)i4 * 4);
    __nv_bfloat16 h[4], l[4];
    split_store(f.x, h[0], l[0]); split_store(f.y, h[1], l[1]);
    split_store(f.z, h[2], l[2]); split_store(f.w, h[3], l[3]);
    *(uint2*)(g_wh + base + (size_t)i4 * 4) = *(uint2*)h;
    *(uint2*)(g_wl + base + (size_t)i4 * 4) = *(uint2*)l;
}

// ===========================================================================
// HMMA projection: q,k,v = x @ W^T via bf16x3 mma.sync.
// CTA: M=128 rows (shared A), 3 outputs x N=64. 8 warps = 4M x 2N,
// warp tile 32x32 per output. K chunks of 64, double-buffered cp.async smem.
// ===========================================================================
#define PSTR 72                       // bf16 elems per smem row (144 B)
#define A_ELE (128 * PSTR)            // 9216 elems
#define B_ELE (64 * PSTR)             // 4608 elems
#define BUF_ELE (2 * A_ELE + 6 * B_ELE)   // 46080 elems
#define PJ_SMEM (2 * BUF_ELE * 2)     // 184320 bytes

__device__ __forceinline__ void pj_load_chunk(uint32_t sbase, int m0, int k0, int buf)
{
    const int tid = threadIdx.x;
    const uint32_t bofs = sbase + buf * BUF_ELE * 2;
    #pragma unroll
    for (int i = 0; i < 4; i++) {                 // A: 1024 uint4 (h) + (l)
        const int idx = tid + 256 * i;
        const int r = idx >> 3, g = idx & 7;
        const size_t go = (size_t)(m0 + r) * DM + k0 + g * 8;
        const uint32_t d = bofs + (r * PSTR + g * 8) * 2;
        cp16(d, g_xh + go);
        cp16(d + A_ELE * 2, g_xl + go);
    }
    #pragma unroll
    for (int i = 0; i < 12; i++) {                // B: 6 tiles x 512 uint4
        const int idx = tid + 256 * i;
        const int t = idx >> 9;                   // 0..5 = o*2 + (0:h,1:l)
        const int rem = idx & 511;
        const int r = rem >> 3, g = rem & 7;
        const int o = t >> 1;
        const __nv_bfloat16* src = ((t & 1) ? g_wl : g_wh)
            + (size_t)o * DH * DM + (size_t)r * DM + k0 + g * 8;
        cp16(bofs + (2 * A_ELE + t * B_ELE + r * PSTR + g * 8) * 2, src);
    }
}

__global__ void __launch_bounds__(256) proj_mma_kernel()
{
    extern __shared__ __nv_bfloat16 smem[];
    const uint32_t sbase = smem_u32(smem);
    const int tid = threadIdx.x;
    const int wid = tid >> 5, lane = tid & 31;
    const int warp_m = wid >> 1, warp_n = wid & 1;
    const int m0 = blockIdx.x * 128;

    float acc[3][2][4][4];
    #pragma unroll
    for (int o = 0; o < 3; o++)
        #pragma unroll
        for (int mt = 0; mt < 2; mt++)
            #pragma unroll
            for (int nt = 0; nt < 4; nt++)
                #pragma unroll
                for (int e = 0; e < 4; e++) acc[o][mt][nt][e] = 0.f;

    pj_load_chunk(sbase, m0, 0, 0);
    CP_COMMIT();
    CP_WAIT0();
    __syncthreads();

    // per-lane ldmatrix address components
    const int arow = lane & 15, ahalf = lane >> 4;          // A 16x16 tiles
    const int bq = lane >> 3, bw = lane & 7;                // B 16x16 quad
    const int brow = (bq >> 1) * 8 + bw;
    const int bk = (bq & 1) * 8;

    for (int c = 0; c < 16; c++) {
        const int buf = c & 1;
        if (c < 15) {
            pj_load_chunk(sbase, m0, (c + 1) * 64, buf ^ 1);
            CP_COMMIT();
        }
        const uint32_t abase = sbase + buf * BUF_ELE * 2;
        #pragma unroll
        for (int ks = 0; ks < 4; ks++) {
            const int kc = ks * 16;
            uint32_t ah[2][4], al[2][4];
            #pragma unroll
            for (int mt = 0; mt < 2; mt++) {
                const uint32_t addr = abase
                    + ((warp_m * 32 + mt * 16 + arow) * PSTR + kc + ahalf * 8) * 2;
                LDMX4(ah[mt], addr);
                LDMX4(al[mt], addr + A_ELE * 2);
            }
            #pragma unroll
            for (int o = 0; o < 3; o++) {
                const uint32_t btile = abase + (2 * A_ELE + (o * 2) * B_ELE) * 2;
                uint32_t bh[2][4], bl[2][4];
                #pragma unroll
                for (int np = 0; np < 2; np++) {
                    const uint32_t addr = btile
                        + ((warp_n * 32 + np * 16 + brow) * PSTR + kc + bk) * 2;
                    LDMX4(bh[np], addr);
                    LDMX4(bl[np], addr + B_ELE * 2);
                }
                #pragma unroll
                for (int mt = 0; mt < 2; mt++)
                    #pragma unroll
                    for (int np = 0; np < 2; np++) {
                        mma16816(acc[o][mt][2 * np],     ah[mt], bh[np][0], bh[np][1]);
                        mma16816(acc[o][mt][2 * np + 1], ah[mt], bh[np][2], bh[np][3]);
                        mma16816(acc[o][mt][2 * np],     ah[mt], bl[np][0], bl[np][1]);
                        mma16816(acc[o][mt][2 * np + 1], ah[mt], bl[np][2], bl[np][3]);
                        mma16816(acc[o][mt][2 * np],     al[mt], bh[np][0], bh[np][1]);
                        mma16816(acc[o][mt][2 * np + 1], al[mt], bh[np][2], bh[np][3]);
                    }
            }
        }
        if (c < 15) CP_WAIT0();
        __syncthreads();
    }

    // epilogue: fragment layout d0,d1 = (row, col..col+1); d2,d3 = row+8
    const int frow = lane >> 2, fcol = (lane & 3) * 2;
    #pragma unroll
    for (int o = 0; o < 3; o++) {
        float* outp = (o == 0) ? g_q : (o == 1) ? g_k : g_v;
        #pragma unroll
        for (int mt = 0; mt < 2; mt++)
            #pragma unroll
            for (int nt = 0; nt < 4; nt++) {
                const int row = m0 + warp_m * 32 + mt * 16 + frow;
                const int col = warp_n * 32 + nt * 8 + fcol;
                float* p = outp + (size_t)row * DH + col;
                *(float2*)(p)            = make_float2(acc[o][mt][nt][0], acc[o][mt][nt][1]);
                *(float2*)(p + 8 * DH)   = make_float2(acc[o][mt][nt][2], acc[o][mt][nt][3]);
            }
    }
}

// ===========================================================================
// FFMA2 helpers for attention (round-4 passing version, unchanged)
// ===========================================================================
__device__ __forceinline__ unsigned long long splat2(float v) {
    unsigned long long r;
    asm("mov.b64 %0, {%1, %1};" : "=l"(r) : "f"(v));
    return r;
}
__device__ __forceinline__ void unpack2(unsigned long long v, float& lo, float& hi) {
    asm("mov.b64 {%0, %1}, %2;" : "=f"(lo), "=f"(hi) : "l"(v));
}
__device__ __forceinline__ void ffma2(unsigned long long& d,
                                      unsigned long long a,
                                      unsigned long long b) {
    asm("fma.rn.f32x2 %0, %1, %2, %0;" : "+l"(d) : "l"(a), "l"(b));
}
#define TILE_FFMA2(acc, a01, a23, bs)                                   \
    {                                                                   \
        _Pragma("unroll")                                               \
        for (int _c = 0; _c < 8; _c++) {                                \
            ffma2(acc[0][_c], a01.x, bs[_c]);                           \
            ffma2(acc[1][_c], a01.y, bs[_c]);                           \
            ffma2(acc[2][_c], a23.x, bs[_c]);                           \
            ffma2(acc[3][_c], a23.y, bs[_c]);                           \
        }                                                               \
    }
#define SPLAT8(bs, b0, b1)                                              \
    unsigned long long bs[8];                                           \
    bs[0] = splat2(b0.x); bs[1] = splat2(b0.y);                         \
    bs[2] = splat2(b0.z); bs[3] = splat2(b0.w);                         \
    bs[4] = splat2(b1.x); bs[5] = splat2(b1.y);                         \
    bs[6] = splat2(b1.z); bs[7] = splat2(b1.w);

// ---------------------------------------------------------------------------
// Split-KV flash attention partial. Br=128, Bc=64, 128 threads, 8x8 tiles.
// ---------------------------------------------------------------------------
#define SQ 132
#define SK 68
#define ASMEM_FLOATS (2 * 64 * SQ + 2 * 64 * SK + 32)
#define ASMEM_BYTES  (ASMEM_FLOATS * 4)

__global__ void __launch_bounds__(128) attn_part_kernel(
    const float* __restrict__ rel_emb)
{
    const int rt    = blockIdx.x;
    const int chunk = blockIdx.y;
    const int b     = blockIdx.z;
    const int ct0   = chunk * 8;
    const int ctmax = 2 * rt + 1;
    if (ct0 > ctmax) return;
    const int ct1 = min(ctmax, ct0 + 7);

    extern __shared__ float sm[];
    float* Qs   = sm;
    float* Ks   = sm + 64 * SQ;
    float* Vs   = Ks + 64 * SK;
    float* Ps   = Vs + 64 * SK;
    float* sRel = Ps + 64 * SQ;

    const int tid = threadIdx.x;
    const int tx  = tid & 7;
    const int ty  = tid >> 3;
    const int i0  = rt * 128;

    if (tid < 17) sRel[tid] = rel_emb[tid];

    #pragma unroll
    for (int it = 0; it < 16; it++) {
        const int idx = tid + 128 * it;
        const int i   = idx >> 4;
        const int hb  = (idx & 15) * 4;
        float4 v = *(const float4*)(g_q + (size_t)(b * TT + i0 + i) * DH + hb);
        Qs[(hb + 0) * SQ + i] = v.x;
        Qs[(hb + 1) * SQ + i] = v.y;
        Qs[(hb + 2) * SQ + i] = v.z;
        Qs[(hb + 3) * SQ + i] = v.w;
    }

    unsigned long long oacc[4][8];
    #pragma unroll
    for (int p = 0; p < 4; p++)
        #pragma unroll
        for (int c = 0; c < 8; c++) oacc[p][c] = 0ull;
    float l_loc[8] = {0.f, 0.f, 0.f, 0.f, 0.f, 0.f, 0.f, 0.f};

    for (int ct = ct0; ct <= ct1; ct++) {
        const int j0 = ct * 64;
        __syncthreads();
        #pragma unroll
        for (int it = 0; it < 8; it++) {
            const int idx = tid + 128 * it;
            const int j   = idx >> 4;
            const int hb  = (idx & 15) * 4;
            float4 kv = *(const float4*)(g_k + (size_t)(b * TT + j0 + j) * DH + hb);
            Ks[(hb + 0) * SK + j] = kv.x;
            Ks[(hb + 1) * SK + j] = kv.y;
            Ks[(hb + 2) * SK + j] = kv.z;
            Ks[(hb + 3) * SK + j] = kv.w;
            float4 vv = *(const float4*)(g_v + (size_t)(b * TT + j0 + j) * DH + hb);
            *(float4*)(&Vs[j * SK + hb]) = vv;
        }
        __syncthreads();

        unsigned long long sacc[4][8];
        #pragma unroll
        for (int p = 0; p < 4; p++)
            #pragma unroll
            for (int c = 0; c < 8; c++) sacc[p][c] = 0ull;
        #pragma unroll 8
        for (int kk = 0; kk < 64; kk++) {
            ulonglong2 a01 = *(const ulonglong2*)(&Qs[kk * SQ + 8 * ty]);
            ulonglong2 a23 = *(const ulonglong2*)(&Qs[kk * SQ + 8 * ty + 4]);
            float4 b0 = *(const float4*)(&Ks[kk * SK + 8 * tx]);
            float4 b1 = *(const float4*)(&Ks[kk * SK + 8 * tx + 4]);
            SPLAT8(bs, b0, b1);
            TILE_FFMA2(sacc, a01, a23, bs);
        }

        const float b0v = sRel[0];
        if (ct <= 2 * rt - 2) {
            #pragma unroll
            for (int c = 0; c < 8; c++) {
                float e[8];
                #pragma unroll
                for (int p = 0; p < 4; p++) {
                    float lo, hi;
                    unpack2(sacc[p][c], lo, hi);
                    e[2 * p]     = __expf(lo * 0.125f + b0v);
                    e[2 * p + 1] = __expf(hi * 0.125f + b0v);
                }
                #pragma unroll
                for (int r = 0; r < 8; r++) l_loc[r] += e[r];
                float* pp = &Ps[(8 * tx + c) * SQ + 8 * ty];
                *(float4*)(pp)     = make_float4(e[0], e[1], e[2], e[3]);
                *(float4*)(pp + 4) = make_float4(e[4], e[5], e[6], e[7]);
            }
        } else {
            const int jb = j0 + 8 * tx;
            const int ib = i0 + 8 * ty;
            #pragma unroll
            for (int c = 0; c < 8; c++) {
                const int j = jb + c;
                float e[8];
                #pragma unroll
                for (int p = 0; p < 4; p++) {
                    float lo, hi;
                    unpack2(sacc[p][c], lo, hi);
                    const int d0 = j - (ib + 2 * p);
                    const int d1 = d0 - 1;
                    e[2 * p]     = (d0 <= 0)
                        ? __expf(lo * 0.125f + sRel[(d0 < -8 ? -8 : d0) + 8]) : 0.f;
                    e[2 * p + 1] = (d1 <= 0)
                        ? __expf(hi * 0.125f + sRel[(d1 < -8 ? -8 : d1) + 8]) : 0.f;
                }
                #pragma unroll
                for (int r = 0; r < 8; r++) l_loc[r] += e[r];
                float* pp = &Ps[(8 * tx + c) * SQ + 8 * ty];
                *(float4*)(pp)     = make_float4(e[0], e[1], e[2], e[3]);
                *(float4*)(pp + 4) = make_float4(e[4], e[5], e[6], e[7]);
            }
        }
        __syncthreads();

        #pragma unroll 8
        for (int jj = 0; jj < 64; jj++) {
            ulonglong2 p01 = *(const ulonglong2*)(&Ps[jj * SQ + 8 * ty]);
            ulonglong2 p23 = *(const ulonglong2*)(&Ps[jj * SQ + 8 * ty + 4]);
            float4 v0 = *(const float4*)(&Vs[jj * SK + 8 * tx]);
            float4 v1 = *(const float4*)(&Vs[jj * SK + 8 * tx + 4]);
            SPLAT8(vs, v0, v1);
            TILE_FFMA2(oacc, p01, p23, vs);
        }
    }

    #pragma unroll
    for (int r = 0; r < 8; r++) {
        float rs = l_loc[r];
        rs += __shfl_xor_sync(0xffffffffu, rs, 1);
        rs += __shfl_xor_sync(0xffffffffu, rs, 2);
        rs += __shfl_xor_sync(0xffffffffu, rs, 4);
        l_loc[r] = rs;
    }

    const size_t unit = ((size_t)(b * 32 + rt) * 8 + chunk);
    float* po = g_po + unit * 128 * 64;
    #pragma unroll
    for (int p = 0; p < 4; p++) {
        float lo[8], hi[8];
        #pragma unroll
        for (int c = 0; c < 8; c++) unpack2(oacc[p][c], lo[c], hi[c]);
        float* o0 = po + (size_t)(8 * ty + 2 * p) * DH + 8 * tx;
        float* o1 = o0 + DH;
        *(float4*)(o0)     = make_float4(lo[0], lo[1], lo[2], lo[3]);
        *(float4*)(o0 + 4) = make_float4(lo[4], lo[5], lo[6], lo[7]);
        *(float4*)(o1)     = make_float4(hi[0], hi[1], hi[2], hi[3]);
        *(float4*)(o1 + 4) = make_float4(hi[4], hi[5], hi[6], hi[7]);
    }
    if (tx == 0) {
        #pragma unroll
        for (int r = 0; r < 8; r++)
            g_pl[unit * 128 + 8 * ty + r] = l_loc[r];
    }
}

// ---------------------------------------------------------------------------
// Combine partials: out = (sum_p O_p) / (sum_p l_p).  Block = (rt, b).
// ---------------------------------------------------------------------------
__global__ void __launch_bounds__(256) combine_kernel(float* __restrict__ out)
{
    const int rt  = blockIdx.x;
    const int b   = blockIdx.y;
    const int nch = (2 * rt + 9) >> 3;
    const size_t base = (size_t)(b * 32 + rt) * 8;

    __shared__ float sInvL[128];

    const int tid = threadIdx.x;
    if (tid < 128) {
        float L = 0.f;
        for (int p = 0; p < nch; p++)
            L += g_pl[(base + p) * 128 + tid];
        sInvL[tid] = 1.0f / L;
    }
    __syncthreads();

    const int r  = tid >> 1;
    const int h0 = (tid & 1) * 32;
    float acc[32] = {};
    for (int p = 0; p < nch; p++) {
        const float* po = g_po + ((base + p) * 128 + r) * 64 + h0;
        #pragma unroll
        for (int u = 0; u < 32; u += 4) {
            float4 v = *(const float4*)(po + u);
            acc[u + 0] += v.x; acc[u + 1] += v.y;
            acc[u + 2] += v.z; acc[u + 3] += v.w;
        }
    }
    const float inv = sInvL[r];
    float* op = out + (size_t)(b * TT + rt * 128 + r) * DH + h0;
    #pragma unroll
    for (int u = 0; u < 32; u += 4)
        *(float4*)(op + u) = make_float4(acc[u] * inv, acc[u + 1] * inv,
                                         acc[u + 2] * inv, acc[u + 3] * inv);
}

extern "C" void kernel_launch(void* const* d_in, const int* in_sizes, int n_in,
                              void* d_out, int out_size)
{
    const float* x   = (const float*)d_in[0];
    const float* Wq  = (const float*)d_in[1];
    const float* Wk  = (const float*)d_in[2];
    const float* Wv  = (const float*)d_in[3];
    const float* rel = (const float*)d_in[4];
    float* out = (float*)d_out;

    convert_x_kernel<<<2048, 256>>>(x);
    dim3 wgrid(64, 3);
    convert_w_kernel<<<wgrid, 256>>>(Wq, Wk, Wv);

    cudaFuncSetAttribute(proj_mma_kernel,
                         cudaFuncAttributeMaxDynamicSharedMemorySize, PJ_SMEM);
    proj_mma_kernel<<<128, 256, PJ_SMEM>>>();

    cudaFuncSetAttribute(attn_part_kernel,
                         cudaFuncAttributeMaxDynamicSharedMemorySize, ASMEM_BYTES);
    dim3 agrid(32, 8, BB);
    attn_part_kernel<<<agrid, 128, ASMEM_BYTES>>>(rel);

    dim3 cgrid(32, BB);
    combine_kernel<<<cgrid, 256>>>(out);
}

// round 8
// speedup vs baseline: 2.3498x; 1.6369x over previous
#include <cuda_runtime.h>
#include <cuda_bf16.h>
#include <cstdint>

#define BB 4
#define TT 4096
#define DM 1024
#define DH 64

// scratch (allocation-free rule: __device__ globals)
// split-KV partials: unit = (b, rt(32 of 128 rows), chunk(8)); O:128x64, l:128
__device__ float g_po[BB * 32 * 8 * 128 * 64];
__device__ float g_pl[BB * 32 * 8 * 128];
// bf16x3 split operands
__device__ __nv_bfloat16 g_xh[BB * TT * DM];
__device__ __nv_bfloat16 g_xl[BB * TT * DM];
__device__ __nv_bfloat16 g_wh[3 * DH * DM];
__device__ __nv_bfloat16 g_wl[3 * DH * DM];
// projection outputs, bf16 hi/lo
__device__ __nv_bfloat16 g_qh[BB * TT * DH];
__device__ __nv_bfloat16 g_ql[BB * TT * DH];
__device__ __nv_bfloat16 g_kh[BB * TT * DH];
__device__ __nv_bfloat16 g_kl[BB * TT * DH];
__device__ __nv_bfloat16 g_vh[BB * TT * DH];
__device__ __nv_bfloat16 g_vl[BB * TT * DH];

// ===========================================================================
// base-ISA helpers: cp.async, ldmatrix, mma.sync (all legal on sm_103)
// ===========================================================================
__device__ __forceinline__ uint32_t smem_u32(const void* p) {
    uint32_t a;
    asm("{ .reg .u64 t; cvta.to.shared.u64 t, %1; cvt.u32.u64 %0, t; }"
        : "=r"(a) : "l"(p));
    return a;
}
__device__ __forceinline__ void cp16(uint32_t dst, const void* src) {
    asm volatile("cp.async.cg.shared.global [%0], [%1], 16;"
                 :: "r"(dst), "l"(src) : "memory");
}
#define CP_COMMIT() asm volatile("cp.async.commit_group;" ::: "memory")
#define CP_WAIT0()  asm volatile("cp.async.wait_group 0;" ::: "memory")

#define LDMX4(r, addr)                                                       \
    asm volatile("ldmatrix.sync.aligned.m8n8.x4.shared.b16 {%0,%1,%2,%3}, [%4];" \
        : "=r"((r)[0]), "=r"((r)[1]), "=r"((r)[2]), "=r"((r)[3]) : "r"(addr))

__device__ __forceinline__ void mma16816(float* d, const uint32_t* a,
                                         uint32_t b0, uint32_t b1) {
    asm volatile(
        "mma.sync.aligned.m16n8k16.row.col.f32.bf16.bf16.f32 "
        "{%0,%1,%2,%3}, {%4,%5,%6,%7}, {%8,%9}, {%0,%1,%2,%3};"
        : "+f"(d[0]), "+f"(d[1]), "+f"(d[2]), "+f"(d[3])
        : "r"(a[0]), "r"(a[1]), "r"(a[2]), "r"(a[3]), "r"(b0), "r"(b1));
}

__device__ __forceinline__ uint32_t packbf2(float flo, float fhi) {
    __nv_bfloat162 h;
    h.x = __float2bfloat16(flo);
    h.y = __float2bfloat16(fhi);
    return *(uint32_t*)&h;
}
__device__ __forceinline__ void split_pack(float f0, float f1,
                                           uint32_t& h, uint32_t& l) {
    __nv_bfloat16 h0 = __float2bfloat16(f0), h1 = __float2bfloat16(f1);
    float r0 = f0 - __bfloat162float(h0), r1 = f1 - __bfloat162float(h1);
    __nv_bfloat162 hp; hp.x = h0; hp.y = h1;
    h = *(uint32_t*)&hp;
    l = packbf2(r0, r1);
}

// ===========================================================================
// convert kernels: fp32 -> (hi, lo) bf16 for x and W
// ===========================================================================
__device__ __forceinline__ void split_store(float f, __nv_bfloat16& h, __nv_bfloat16& l) {
    h = __float2bfloat16(f);
    l = __float2bfloat16(f - __bfloat162float(h));
}
__global__ void __launch_bounds__(256) convert_x_kernel(const float* __restrict__ x)
{
    const int stride = gridDim.x * 256;
    for (int i4 = blockIdx.x * 256 + threadIdx.x; i4 < BB * TT * DM / 4; i4 += stride) {
        float4 f = *(const float4*)(x + (size_t)i4 * 4);
        __nv_bfloat16 h[4], l[4];
        split_store(f.x, h[0], l[0]); split_store(f.y, h[1], l[1]);
        split_store(f.z, h[2], l[2]); split_store(f.w, h[3], l[3]);
        *(uint2*)(g_xh + (size_t)i4 * 4) = *(uint2*)h;
        *(uint2*)(g_xl + (size_t)i4 * 4) = *(uint2*)l;
    }
}
__global__ void __launch_bounds__(256) convert_w_kernel(
    const float* __restrict__ Wq, const float* __restrict__ Wk,
    const float* __restrict__ Wv)
{
    const float* W = (blockIdx.y == 0) ? Wq : (blockIdx.y == 1) ? Wk : Wv;
    const size_t base = (size_t)blockIdx.y * DH * DM;
    const int i4 = blockIdx.x * 256 + threadIdx.x;
    float4 f = *(const float4*)(W + (size_t)i4 * 4);
    __nv_bfloat16 h[4], l[4];
    split_store(f.x, h[0], l[0]); split_store(f.y, h[1], l[1]);
    split_store(f.z, h[2], l[2]); split_store(f.w, h[3], l[3]);
    *(uint2*)(g_wh + base + (size_t)i4 * 4) = *(uint2*)h;
    *(uint2*)(g_wl + base + (size_t)i4 * 4) = *(uint2*)l;
}

// ===========================================================================
// HMMA projection: q,k,v = x @ W^T via bf16x3 mma.sync.
// CTA: M=128 rows (shared A), 3 outputs x N=64. 8 warps = 4M x 2N.
// Epilogue writes bf16 hi/lo splits of q/k/v.
// ===========================================================================
#define PSTR 72
#define A_ELE (128 * PSTR)
#define B_ELE (64 * PSTR)
#define BUF_ELE (2 * A_ELE + 6 * B_ELE)
#define PJ_SMEM (2 * BUF_ELE * 2)

__device__ __forceinline__ void pj_load_chunk(uint32_t sbase, int m0, int k0, int buf)
{
    const int tid = threadIdx.x;
    const uint32_t bofs = sbase + buf * BUF_ELE * 2;
    #pragma unroll
    for (int i = 0; i < 4; i++) {
        const int idx = tid + 256 * i;
        const int r = idx >> 3, g = idx & 7;
        const size_t go = (size_t)(m0 + r) * DM + k0 + g * 8;
        const uint32_t d = bofs + (r * PSTR + g * 8) * 2;
        cp16(d, g_xh + go);
        cp16(d + A_ELE * 2, g_xl + go);
    }
    #pragma unroll
    for (int i = 0; i < 12; i++) {
        const int idx = tid + 256 * i;
        const int t = idx >> 9;
        const int rem = idx & 511;
        const int r = rem >> 3, g = rem & 7;
        const int o = t >> 1;
        const __nv_bfloat16* src = ((t & 1) ? g_wl : g_wh)
            + (size_t)o * DH * DM + (size_t)r * DM + k0 + g * 8;
        cp16(bofs + (2 * A_ELE + t * B_ELE + r * PSTR + g * 8) * 2, src);
    }
}

__global__ void __launch_bounds__(256) proj_mma_kernel()
{
    extern __shared__ __nv_bfloat16 smem[];
    const uint32_t sbase = smem_u32(smem);
    const int tid = threadIdx.x;
    const int wid = tid >> 5, lane = tid & 31;
    const int warp_m = wid >> 1, warp_n = wid & 1;
    const int m0 = blockIdx.x * 128;

    float acc[3][2][4][4];
    #pragma unroll
    for (int o = 0; o < 3; o++)
        #pragma unroll
        for (int mt = 0; mt < 2; mt++)
            #pragma unroll
            for (int nt = 0; nt < 4; nt++)
                #pragma unroll
                for (int e = 0; e < 4; e++) acc[o][mt][nt][e] = 0.f;

    pj_load_chunk(sbase, m0, 0, 0);
    CP_COMMIT();
    CP_WAIT0();
    __syncthreads();

    const int arow = lane & 15, ahalf = lane >> 4;
    const int bq = lane >> 3, bw = lane & 7;
    const int brow = (bq >> 1) * 8 + bw;
    const int bk = (bq & 1) * 8;

    for (int c = 0; c < 16; c++) {
        const int buf = c & 1;
        if (c < 15) {
            pj_load_chunk(sbase, m0, (c + 1) * 64, buf ^ 1);
            CP_COMMIT();
        }
        const uint32_t abase = sbase + buf * BUF_ELE * 2;
        #pragma unroll
        for (int ks = 0; ks < 4; ks++) {
            const int kc = ks * 16;
            uint32_t ah[2][4], al[2][4];
            #pragma unroll
            for (int mt = 0; mt < 2; mt++) {
                const uint32_t addr = abase
                    + ((warp_m * 32 + mt * 16 + arow) * PSTR + kc + ahalf * 8) * 2;
                LDMX4(ah[mt], addr);
                LDMX4(al[mt], addr + A_ELE * 2);
            }
            #pragma unroll
            for (int o = 0; o < 3; o++) {
                const uint32_t btile = abase + (2 * A_ELE + (o * 2) * B_ELE) * 2;
                uint32_t bh[2][4], bl[2][4];
                #pragma unroll
                for (int np = 0; np < 2; np++) {
                    const uint32_t addr = btile
                        + ((warp_n * 32 + np * 16 + brow) * PSTR + kc + bk) * 2;
                    LDMX4(bh[np], addr);
                    LDMX4(bl[np], addr + B_ELE * 2);
                }
                #pragma unroll
                for (int mt = 0; mt < 2; mt++)
                    #pragma unroll
                    for (int np = 0; np < 2; np++) {
                        mma16816(acc[o][mt][2 * np],     ah[mt], bh[np][0], bh[np][1]);
                        mma16816(acc[o][mt][2 * np + 1], ah[mt], bh[np][2], bh[np][3]);
                        mma16816(acc[o][mt][2 * np],     ah[mt], bl[np][0], bl[np][1]);
                        mma16816(acc[o][mt][2 * np + 1], ah[mt], bl[np][2], bl[np][3]);
                        mma16816(acc[o][mt][2 * np],     al[mt], bh[np][0], bh[np][1]);
                        mma16816(acc[o][mt][2 * np + 1], al[mt], bh[np][2], bh[np][3]);
                    }
            }
        }
        if (c < 15) CP_WAIT0();
        __syncthreads();
    }

    // epilogue: write bf16 hi/lo splits directly
    const int frow = lane >> 2, fcol = (lane & 3) * 2;
    #pragma unroll
    for (int o = 0; o < 3; o++) {
        __nv_bfloat16* oh = (o == 0) ? g_qh : (o == 1) ? g_kh : g_vh;
        __nv_bfloat16* ol = (o == 0) ? g_ql : (o == 1) ? g_kl : g_vl;
        #pragma unroll
        for (int mt = 0; mt < 2; mt++)
            #pragma unroll
            for (int nt = 0; nt < 4; nt++) {
                const int row = m0 + warp_m * 32 + mt * 16 + frow;
                const int col = warp_n * 32 + nt * 8 + fcol;
                uint32_t h01, l01, h23, l23;
                split_pack(acc[o][mt][nt][0], acc[o][mt][nt][1], h01, l01);
                split_pack(acc[o][mt][nt][2], acc[o][mt][nt][3], h23, l23);
                *(uint32_t*)(oh + (size_t)row * DH + col) = h01;
                *(uint32_t*)(ol + (size_t)row * DH + col) = l01;
                *(uint32_t*)(oh + (size_t)(row + 8) * DH + col) = h23;
                *(uint32_t*)(ol + (size_t)(row + 8) * DH + col) = l23;
            }
    }
}

// ===========================================================================
// HMMA split-KV flash attention. Br=128, Bc=64, 256 thr (8 warps x 16 rows).
// QK^T and PV both bf16x3 mma.sync; P kept in registers (accum->A reuse).
// ===========================================================================
#define AST 72
#define AT_QH 0
#define AT_QL (128 * AST)
#define AT_KH (2 * 128 * AST)
#define AT_KL (AT_KH + 64 * AST)
#define AT_VH (AT_KL + 64 * AST)
#define AT_VL (AT_VH + 64 * AST)
#define AT_ELEMS (AT_VL + 64 * AST)
#define AT_SMEM (AT_ELEMS * 2)   // 73728 bytes

__global__ void __launch_bounds__(256) attn_mma_kernel(
    const float* __restrict__ rel_emb)
{
    const int rt    = blockIdx.x;       // 0..31
    const int chunk = blockIdx.y;       // 0..7
    const int b     = blockIdx.z;
    const int ct0   = chunk * 8;
    const int ctmax = 2 * rt + 1;
    if (ct0 > ctmax) return;
    const int ct1 = min(ctmax, ct0 + 7);

    extern __shared__ __nv_bfloat16 asb[];
    const uint32_t sbase = smem_u32(asb);
    __shared__ float sRel[17];

    const int tid = threadIdx.x;
    const int w = tid >> 5, lane = tid & 31;
    const int i0 = rt * 128;

    if (tid < 17) sRel[tid] = rel_emb[tid];

    // load Q tile (hi+lo) via cp.async: rows i0..i0+127, 64 cols
    #pragma unroll
    for (int it = 0; it < 4; it++) {
        const int idx = tid + 256 * it;
        const int r = idx >> 3, g = idx & 7;
        const size_t go = (size_t)(b * TT + i0 + r) * DH + g * 8;
        const uint32_t so = (r * AST + g * 8) * 2;
        cp16(sbase + AT_QH * 2 + so, g_qh + go);
        cp16(sbase + AT_QL * 2 + so, g_ql + go);
    }
    CP_COMMIT();

    const int arow = lane & 15, ahalf = lane >> 4;
    const int bq = lane >> 3, bw = lane & 7;
    const int brow = (bq >> 1) * 8 + bw;
    const int bk = (bq & 1) * 8;
    const int frow = lane >> 2, fcol = (lane & 3) * 2;

    float oacc[8][4];
    #pragma unroll
    for (int nt = 0; nt < 8; nt++)
        #pragma unroll
        for (int e = 0; e < 4; e++) oacc[nt][e] = 0.f;
    float l0 = 0.f, l1 = 0.f;

    for (int ct = ct0; ct <= ct1; ct++) {
        const int j0 = ct * 64;
        // load K tile (hi+lo)
        #pragma unroll
        for (int it = 0; it < 2; it++) {
            const int idx = tid + 256 * it;
            const int r = idx >> 3, g = idx & 7;
            const size_t go = (size_t)(b * TT + j0 + r) * DH + g * 8;
            const uint32_t so = (r * AST + g * 8) * 2;
            cp16(sbase + AT_KH * 2 + so, g_kh + go);
            cp16(sbase + AT_KL * 2 + so, g_kl + go);
        }
        CP_COMMIT();
        // load V transposed: Vt[h][j]
        #pragma unroll
        for (int it = 0; it < 4; it++) {
            const int idx = tid + 256 * it;
            const int j = idx >> 4;
            const int hb = (idx & 15) * 4;
            const size_t go = (size_t)(b * TT + j0 + j) * DH + hb;
            uint2 vh = *(const uint2*)(g_vh + go);
            uint2 vl = *(const uint2*)(g_vl + go);
            const __nv_bfloat16* ph = (const __nv_bfloat16*)&vh;
            const __nv_bfloat16* pl = (const __nv_bfloat16*)&vl;
            #pragma unroll
            for (int u = 0; u < 4; u++) {
                asb[AT_VH + (hb + u) * AST + j] = ph[u];
                asb[AT_VL + (hb + u) * AST + j] = pl[u];
            }
        }
        CP_WAIT0();
        __syncthreads();

        // ---- S = Q K^T ----
        float sacc[8][4];
        #pragma unroll
        for (int nt = 0; nt < 8; nt++)
            #pragma unroll
            for (int e = 0; e < 4; e++) sacc[nt][e] = 0.f;
        #pragma unroll
        for (int ks = 0; ks < 4; ks++) {
            const int kc = ks * 16;
            uint32_t ah[4], al[4];
            const uint32_t aaddr = sbase
                + ((w * 16 + arow) * AST + kc + ahalf * 8) * 2;
            LDMX4(ah, aaddr + AT_QH * 2);
            LDMX4(al, aaddr + AT_QL * 2);
            #pragma unroll
            for (int nt16 = 0; nt16 < 4; nt16++) {
                uint32_t bh[4], bl[4];
                const uint32_t baddr = sbase
                    + ((nt16 * 16 + brow) * AST + kc + bk) * 2;
                LDMX4(bh, baddr + AT_KH * 2);
                LDMX4(bl, baddr + AT_KL * 2);
                mma16816(sacc[2 * nt16],     ah, bh[0], bh[1]);
                mma16816(sacc[2 * nt16 + 1], ah, bh[2], bh[3]);
                mma16816(sacc[2 * nt16],     ah, bl[0], bl[1]);
                mma16816(sacc[2 * nt16 + 1], ah, bl[2], bl[3]);
                mma16816(sacc[2 * nt16],     al, bh[0], bh[1]);
                mma16816(sacc[2 * nt16 + 1], al, bh[2], bh[3]);
            }
        }

        // ---- bias + exp (+ mask), accumulate l ----
        float e[8][4];
        const float b0v = sRel[0];
        if (ct <= 2 * rt - 2) {
            #pragma unroll
            for (int nt = 0; nt < 8; nt++)
                #pragma unroll
                for (int u = 0; u < 4; u++)
                    e[nt][u] = __expf(sacc[nt][u] * 0.125f + b0v);
        } else {
            const int ia = i0 + w * 16 + frow;
            #pragma unroll
            for (int nt = 0; nt < 8; nt++) {
                const int jb2 = j0 + nt * 8 + fcol;
                #pragma unroll
                for (int u = 0; u < 4; u++) {
                    const int j = jb2 + (u & 1);
                    const int i = ia + (u >> 1) * 8;
                    const int d = j - i;
                    e[nt][u] = (d <= 0)
                        ? __expf(sacc[nt][u] * 0.125f + sRel[(d < -8 ? -8 : d) + 8])
                        : 0.f;
                }
            }
        }
        #pragma unroll
        for (int nt = 0; nt < 8; nt++) {
            l0 += e[nt][0] + e[nt][1];
            l1 += e[nt][2] + e[nt][3];
        }

        // ---- P fragments (register reuse: accum layout == A layout) ----
        uint32_t pah[4][4], pal[4][4];
        #pragma unroll
        for (int t = 0; t < 4; t++) {
            split_pack(e[2 * t][0],     e[2 * t][1],     pah[t][0], pal[t][0]);
            split_pack(e[2 * t][2],     e[2 * t][3],     pah[t][1], pal[t][1]);
            split_pack(e[2 * t + 1][0], e[2 * t + 1][1], pah[t][2], pal[t][2]);
            split_pack(e[2 * t + 1][2], e[2 * t + 1][3], pah[t][3], pal[t][3]);
        }

        // ---- O += P V ----
        #pragma unroll
        for (int js = 0; js < 4; js++) {
            const int jc = js * 16;
            #pragma unroll
            for (int h16 = 0; h16 < 4; h16++) {
                uint32_t vh4[4], vl4[4];
                const uint32_t vaddr = sbase
                    + ((h16 * 16 + brow) * AST + jc + bk) * 2;
                LDMX4(vh4, vaddr + AT_VH * 2);
                LDMX4(vl4, vaddr + AT_VL * 2);
                mma16816(oacc[2 * h16],     pah[js], vh4[0], vh4[1]);
                mma16816(oacc[2 * h16 + 1], pah[js], vh4[2], vh4[3]);
                mma16816(oacc[2 * h16],     pah[js], vl4[0], vl4[1]);
                mma16816(oacc[2 * h16 + 1], pah[js], vl4[2], vl4[3]);
                mma16816(oacc[2 * h16],     pal[js], vh4[0], vh4[1]);
                mma16816(oacc[2 * h16 + 1], pal[js], vh4[2], vh4[3]);
            }
        }
        __syncthreads();
    }

    // reduce l within quads (lanes sharing rows)
    l0 += __shfl_xor_sync(0xffffffffu, l0, 1);
    l0 += __shfl_xor_sync(0xffffffffu, l0, 2);
    l1 += __shfl_xor_sync(0xffffffffu, l1, 1);
    l1 += __shfl_xor_sync(0xffffffffu, l1, 2);

    // write partials
    const size_t unit = ((size_t)(b * 32 + rt) * 8 + chunk);
    float* po = g_po + unit * 128 * 64;
    const int row = w * 16 + frow;
    #pragma unroll
    for (int nt = 0; nt < 8; nt++) {
        const int col = nt * 8 + fcol;
        *(float2*)(po + (size_t)row * 64 + col) =
            make_float2(oacc[nt][0], oacc[nt][1]);
        *(float2*)(po + (size_t)(row + 8) * 64 + col) =
            make_float2(oacc[nt][2], oacc[nt][3]);
    }
    if ((lane & 3) == 0) {
        g_pl[unit * 128 + row] = l0;
        g_pl[unit * 128 + row + 8] = l1;
    }
}

// ---------------------------------------------------------------------------
// Combine partials: out = (sum_p O_p) / (sum_p l_p).  Block = (rt, b).
// ---------------------------------------------------------------------------
__global__ void __launch_bounds__(256) combine_kernel(float* __restrict__ out)
{
    const int rt  = blockIdx.x;
    const int b   = blockIdx.y;
    const int nch = (2 * rt + 9) >> 3;
    const size_t base = (size_t)(b * 32 + rt) * 8;

    __shared__ float sInvL[128];

    const int tid = threadIdx.x;
    if (tid < 128) {
        float L = 0.f;
        for (int p = 0; p < nch; p++)
            L += g_pl[(base + p) * 128 + tid];
        sInvL[tid] = 1.0f / L;
    }
    __syncthreads();

    const int r  = tid >> 1;
    const int h0 = (tid & 1) * 32;
    float acc[32] = {};
    for (int p = 0; p < nch; p++) {
        const float* po = g_po + ((base + p) * 128 + r) * 64 + h0;
        #pragma unroll
        for (int u = 0; u < 32; u += 4) {
            float4 v = *(const float4*)(po + u);
            acc[u + 0] += v.x; acc[u + 1] += v.y;
            acc[u + 2] += v.z; acc[u + 3] += v.w;
        }
    }
    const float inv = sInvL[r];
    float* op = out + (size_t)(b * TT + rt * 128 + r) * DH + h0;
    #pragma unroll
    for (int u = 0; u < 32; u += 4)
        *(float4*)(op + u) = make_float4(acc[u] * inv, acc[u + 1] * inv,
                                         acc[u + 2] * inv, acc[u + 3] * inv);
}

extern "C" void kernel_launch(void* const* d_in, const int* in_sizes, int n_in,
                              void* d_out, int out_size)
{
    const float* x   = (const float*)d_in[0];
    const float* Wq  = (const float*)d_in[1];
    const float* Wk  = (const float*)d_in[2];
    const float* Wv  = (const float*)d_in[3];
    const float* rel = (const float*)d_in[4];
    float* out = (float*)d_out;

    convert_x_kernel<<<2048, 256>>>(x);
    dim3 wgrid(64, 3);
    convert_w_kernel<<<wgrid, 256>>>(Wq, Wk, Wv);

    cudaFuncSetAttribute(proj_mma_kernel,
                         cudaFuncAttributeMaxDynamicSharedMemorySize, PJ_SMEM);
    proj_mma_kernel<<<128, 256, PJ_SMEM>>>();

    cudaFuncSetAttribute(attn_mma_kernel,
                         cudaFuncAttributeMaxDynamicSharedMemorySize, AT_SMEM);
    dim3 agrid(32, 8, BB);
    attn_mma_kernel<<<agrid, 256, AT_SMEM>>>(rel);

    dim3 cgrid(32, BB);
    combine_kernel<<<cgrid, 256>>>(out);
}

// round 9
// speedup vs baseline: 3.0518x; 1.2987x over previous
#include <cuda_runtime.h>
#include <cuda_bf16.h>
#include <cstdint>

#define BB 4
#define TT 4096
#define DM 1024
#define DH 64

// scratch (allocation-free rule: __device__ globals)
__device__ float g_po[BB * 32 * 8 * 128 * 64];
__device__ float g_pl[BB * 32 * 8 * 128];
__device__ __nv_bfloat16 g_wh[3 * DH * DM];
__device__ __nv_bfloat16 g_wl[3 * DH * DM];
__device__ __nv_bfloat16 g_qh[BB * TT * DH];
__device__ __nv_bfloat16 g_ql[BB * TT * DH];
__device__ __nv_bfloat16 g_kh[BB * TT * DH];
__device__ __nv_bfloat16 g_kl[BB * TT * DH];
__device__ __nv_bfloat16 g_vh[BB * TT * DH];
__device__ __nv_bfloat16 g_vl[BB * TT * DH];

// ===========================================================================
// base-ISA helpers
// ===========================================================================
__device__ __forceinline__ uint32_t smem_u32(const void* p) {
    uint32_t a;
    asm("{ .reg .u64 t; cvta.to.shared.u64 t, %1; cvt.u32.u64 %0, t; }"
        : "=r"(a) : "l"(p));
    return a;
}
__device__ __forceinline__ void cp16(uint32_t dst, const void* src) {
    asm volatile("cp.async.cg.shared.global [%0], [%1], 16;"
                 :: "r"(dst), "l"(src) : "memory");
}
#define CP_COMMIT() asm volatile("cp.async.commit_group;" ::: "memory")
#define CP_WAIT0()  asm volatile("cp.async.wait_group 0;" ::: "memory")
#define CP_WAIT1()  asm volatile("cp.async.wait_group 1;" ::: "memory")

#define LDMX4(r, addr)                                                       \
    asm volatile("ldmatrix.sync.aligned.m8n8.x4.shared.b16 {%0,%1,%2,%3}, [%4];" \
        : "=r"((r)[0]), "=r"((r)[1]), "=r"((r)[2]), "=r"((r)[3]) : "r"(addr))
#define LDMX4T(r, addr)                                                      \
    asm volatile("ldmatrix.sync.aligned.m8n8.x4.trans.shared.b16 {%0,%1,%2,%3}, [%4];" \
        : "=r"((r)[0]), "=r"((r)[1]), "=r"((r)[2]), "=r"((r)[3]) : "r"(addr))

__device__ __forceinline__ void mma16816(float* d, const uint32_t* a,
                                         uint32_t b0, uint32_t b1) {
    asm volatile(
        "mma.sync.aligned.m16n8k16.row.col.f32.bf16.bf16.f32 "
        "{%0,%1,%2,%3}, {%4,%5,%6,%7}, {%8,%9}, {%0,%1,%2,%3};"
        : "+f"(d[0]), "+f"(d[1]), "+f"(d[2]), "+f"(d[3])
        : "r"(a[0]), "r"(a[1]), "r"(a[2]), "r"(a[3]), "r"(b0), "r"(b1));
}

__device__ __forceinline__ uint32_t packbf2(float flo, float fhi) {
    __nv_bfloat162 h;
    h.x = __float2bfloat16(flo);
    h.y = __float2bfloat16(fhi);
    return *(uint32_t*)&h;
}
__device__ __forceinline__ void split_pack(float f0, float f1,
                                           uint32_t& h, uint32_t& l) {
    __nv_bfloat16 h0 = __float2bfloat16(f0), h1 = __float2bfloat16(f1);
    float r0 = f0 - __bfloat162float(h0), r1 = f1 - __bfloat162float(h1);
    __nv_bfloat162 hp; hp.x = h0; hp.y = h1;
    h = *(uint32_t*)&hp;
    l = packbf2(r0, r1);
}
__device__ __forceinline__ void split_store(float f, __nv_bfloat16& h, __nv_bfloat16& l) {
    h = __float2bfloat16(f);
    l = __float2bfloat16(f - __bfloat162float(h));
}

// ===========================================================================
// convert W: fp32 -> (hi, lo) bf16
// ===========================================================================
__global__ void __launch_bounds__(256) convert_w_kernel(
    const float* __restrict__ Wq, const float* __restrict__ Wk,
    const float* __restrict__ Wv)
{
    const float* W = (blockIdx.y == 0) ? Wq : (blockIdx.y == 1) ? Wk : Wv;
    const size_t base = (size_t)blockIdx.y * DH * DM;
    const int i4 = blockIdx.x * 256 + threadIdx.x;
    float4 f = *(const float4*)(W + (size_t)i4 * 4);
    __nv_bfloat16 h[4], l[4];
    split_store(f.x, h[0], l[0]); split_store(f.y, h[1], l[1]);
    split_store(f.z, h[2], l[2]); split_store(f.w, h[3], l[3]);
    *(uint2*)(g_wh + base + (size_t)i4 * 4) = *(uint2*)h;
    *(uint2*)(g_wl + base + (size_t)i4 * 4) = *(uint2*)l;
}

// ===========================================================================
// HMMA projection with fused x-conversion.
// CTA: M=128 rows, 3 outputs x N=64. 8 warps = 4M x 2N. K chunks of 64.
// A: fp32 x LDG -> in-register split -> bf16 hi/lo smem. B: cp.async bf16.
// ===========================================================================
#define PSTR 72
#define A_ELE (128 * PSTR)
#define B_ELE (64 * PSTR)
#define BUF_ELE (2 * A_ELE + 6 * B_ELE)
#define PJ_SMEM (2 * BUF_ELE * 2)

__device__ __forceinline__ void pj_load_B(uint32_t sbase, int k0, int buf)
{
    const int tid = threadIdx.x;
    const uint32_t bofs = sbase + buf * BUF_ELE * 2;
    #pragma unroll
    for (int i = 0; i < 12; i++) {
        const int idx = tid + 256 * i;
        const int t = idx >> 9;
        const int rem = idx & 511;
        const int r = rem >> 3, g = rem & 7;
        const int o = t >> 1;
        const __nv_bfloat16* src = ((t & 1) ? g_wl : g_wh)
            + (size_t)o * DH * DM + (size_t)r * DM + k0 + g * 8;
        cp16(bofs + (2 * A_ELE + t * B_ELE + r * PSTR + g * 8) * 2, src);
    }
}

__device__ __forceinline__ void pj_load_A_regs(const float* __restrict__ x,
                                               int m0, int k0, float4* ra)
{
    const int tid = threadIdx.x;
    #pragma unroll
    for (int i = 0; i < 8; i++) {
        const int idx = tid + 256 * i;
        const int r = idx >> 4, g = idx & 15;
        ra[i] = *(const float4*)(x + (size_t)(m0 + r) * DM + k0 + g * 4);
    }
}
__device__ __forceinline__ void pj_store_A(char* smembytes, const float4* ra, int buf)
{
    const int tid = threadIdx.x;
    const uint32_t bofs = buf * BUF_ELE * 2;
    #pragma unroll
    for (int i = 0; i < 8; i++) {
        const int idx = tid + 256 * i;
        const int r = idx >> 4, g = idx & 15;
        __nv_bfloat16 h[4], l[4];
        split_store(ra[i].x, h[0], l[0]); split_store(ra[i].y, h[1], l[1]);
        split_store(ra[i].z, h[2], l[2]); split_store(ra[i].w, h[3], l[3]);
        const uint32_t so = (r * PSTR + g * 4) * 2;
        *(uint2*)(smembytes + bofs + so) = *(uint2*)h;
        *(uint2*)(smembytes + bofs + A_ELE * 2 + so) = *(uint2*)l;
    }
}

__global__ void __launch_bounds__(256) proj_mma_kernel(const float* __restrict__ x)
{
    extern __shared__ char smemb[];
    const uint32_t sbase = smem_u32(smemb);
    const int tid = threadIdx.x;
    const int wid = tid >> 5, lane = tid & 31;
    const int warp_m = wid >> 1, warp_n = wid & 1;
    const int m0 = blockIdx.x * 128;

    float acc[3][2][4][4];
    #pragma unroll
    for (int o = 0; o < 3; o++)
        #pragma unroll
        for (int mt = 0; mt < 2; mt++)
            #pragma unroll
            for (int nt = 0; nt < 4; nt++)
                #pragma unroll
                for (int e = 0; e < 4; e++) acc[o][mt][nt][e] = 0.f;

    float4 ra[8];
    pj_load_A_regs(x, m0, 0, ra);
    pj_load_B(sbase, 0, 0);
    CP_COMMIT();
    pj_store_A(smemb, ra, 0);
    CP_WAIT0();
    __syncthreads();

    const int arow = lane & 15, ahalf = lane >> 4;
    const int bq = lane >> 3, bw = lane & 7;
    const int brow = (bq >> 1) * 8 + bw;
    const int bk = (bq & 1) * 8;

    for (int c = 0; c < 16; c++) {
        const int buf = c & 1;
        if (c < 15) {
            pj_load_A_regs(x, m0, (c + 1) * 64, ra);
            pj_load_B(sbase, (c + 1) * 64, buf ^ 1);
            CP_COMMIT();
        }
        const uint32_t abase = sbase + buf * BUF_ELE * 2;
        #pragma unroll
        for (int ks = 0; ks < 4; ks++) {
            const int kc = ks * 16;
            uint32_t ah[2][4], al[2][4];
            #pragma unroll
            for (int mt = 0; mt < 2; mt++) {
                const uint32_t addr = abase
                    + ((warp_m * 32 + mt * 16 + arow) * PSTR + kc + ahalf * 8) * 2;
                LDMX4(ah[mt], addr);
                LDMX4(al[mt], addr + A_ELE * 2);
            }
            #pragma unroll
            for (int o = 0; o < 3; o++) {
                const uint32_t btile = abase + (2 * A_ELE + (o * 2) * B_ELE) * 2;
                uint32_t bh[2][4], bl[2][4];
                #pragma unroll
                for (int np = 0; np < 2; np++) {
                    const uint32_t addr = btile
                        + ((warp_n * 32 + np * 16 + brow) * PSTR + kc + bk) * 2;
                    LDMX4(bh[np], addr);
                    LDMX4(bl[np], addr + B_ELE * 2);
                }
                #pragma unroll
                for (int mt = 0; mt < 2; mt++)
                    #pragma unroll
                    for (int np = 0; np < 2; np++) {
                        mma16816(acc[o][mt][2 * np],     ah[mt], bh[np][0], bh[np][1]);
                        mma16816(acc[o][mt][2 * np + 1], ah[mt], bh[np][2], bh[np][3]);
                        mma16816(acc[o][mt][2 * np],     ah[mt], bl[np][0], bl[np][1]);
                        mma16816(acc[o][mt][2 * np + 1], ah[mt], bl[np][2], bl[np][3]);
                        mma16816(acc[o][mt][2 * np],     al[mt], bh[np][0], bh[np][1]);
                        mma16816(acc[o][mt][2 * np + 1], al[mt], bh[np][2], bh[np][3]);
                    }
            }
        }
        if (c < 15) {
            pj_store_A(smemb, ra, buf ^ 1);
            CP_WAIT0();
        }
        __syncthreads();
    }

    // epilogue: write bf16 hi/lo splits
    const int frow = lane >> 2, fcol = (lane & 3) * 2;
    #pragma unroll
    for (int o = 0; o < 3; o++) {
        __nv_bfloat16* oh = (o == 0) ? g_qh : (o == 1) ? g_kh : g_vh;
        __nv_bfloat16* ol = (o == 0) ? g_ql : (o == 1) ? g_kl : g_vl;
        #pragma unroll
        for (int mt = 0; mt < 2; mt++)
            #pragma unroll
            for (int nt = 0; nt < 4; nt++) {
                const int row = m0 + warp_m * 32 + mt * 16 + frow;
                const int col = warp_n * 32 + nt * 8 + fcol;
                uint32_t h01, l01, h23, l23;
                split_pack(acc[o][mt][nt][0], acc[o][mt][nt][1], h01, l01);
                split_pack(acc[o][mt][nt][2], acc[o][mt][nt][3], h23, l23);
                *(uint32_t*)(oh + (size_t)row * DH + col) = h01;
                *(uint32_t*)(ol + (size_t)row * DH + col) = l01;
                *(uint32_t*)(oh + (size_t)(row + 8) * DH + col) = h23;
                *(uint32_t*)(ol + (size_t)(row + 8) * DH + col) = l23;
            }
    }
}

// ===========================================================================
// HMMA split-KV flash attention, pipelined. Br=128, Bc=64, 256 thr.
// K/V double-buffered cp.async; V natural layout + ldmatrix.trans.
// ===========================================================================
#define AST 72
#define AT_QH 0
#define AT_QL 9216
#define AT_TB 18432            // tile buffers start (elems)
#define AT_TBSZ 18432          // per-buffer elems: KH|KL|VH|VL each 4608
#define AT_SMEM ((AT_TB + 2 * AT_TBSZ) * 2)   // 110592 bytes

__device__ __forceinline__ void at_load(uint32_t sbase, int b, int j0, int buf)
{
    const int tid = threadIdx.x;
    const uint32_t bb = sbase + (AT_TB + buf * AT_TBSZ) * 2;
    #pragma unroll
    for (int i = 0; i < 2; i++) {
        const int idx = tid + 256 * i;
        const int r = idx >> 3, g = idx & 7;
        const size_t go = (size_t)(b * TT + j0 + r) * DH + g * 8;
        const uint32_t so = (r * AST + g * 8) * 2;
        cp16(bb + so,         g_kh + go);
        cp16(bb + 9216 + so,  g_kl + go);
        cp16(bb + 18432 + so, g_vh + go);
        cp16(bb + 27648 + so, g_vl + go);
    }
}

__global__ void __launch_bounds__(256) attn_mma_kernel(
    const float* __restrict__ rel_emb)
{
    const int rt    = blockIdx.x;
    const int chunk = blockIdx.y;
    const int b     = blockIdx.z;
    const int ct0   = chunk * 8;
    const int ctmax = 2 * rt + 1;
    if (ct0 > ctmax) return;
    const int ct1 = min(ctmax, ct0 + 7);

    extern __shared__ char smemb[];
    const uint32_t sbase = smem_u32(smemb);
    __shared__ float sRel[17];

    const int tid = threadIdx.x;
    const int w = tid >> 5, lane = tid & 31;
    const int i0 = rt * 128;

    if (tid < 17) sRel[tid] = rel_emb[tid];

    // Q tile (hi+lo) + first K/V tile in commit-group 0
    #pragma unroll
    for (int it = 0; it < 4; it++) {
        const int idx = tid + 256 * it;
        const int r = idx >> 3, g = idx & 7;
        const size_t go = (size_t)(b * TT + i0 + r) * DH + g * 8;
        const uint32_t so = (r * AST + g * 8) * 2;
        cp16(sbase + AT_QH * 2 + so, g_qh + go);
        cp16(sbase + AT_QL * 2 + so, g_ql + go);
    }
    at_load(sbase, b, ct0 * 64, 0);
    CP_COMMIT();

    const int arow = lane & 15, ahalf = lane >> 4;
    const int bq = lane >> 3, bw = lane & 7;
    const int brow = (bq >> 1) * 8 + bw;
    const int bk = (bq & 1) * 8;
    const int frow = lane >> 2, fcol = (lane & 3) * 2;
    const int vrow = (bq & 1) * 8 + bw;     // j-part for trans V load
    const int vcol = (bq >> 1) * 8;         // h-part

    float oacc[8][4];
    #pragma unroll
    for (int nt = 0; nt < 8; nt++)
        #pragma unroll
        for (int e = 0; e < 4; e++) oacc[nt][e] = 0.f;
    float l0 = 0.f, l1 = 0.f;

    for (int ct = ct0; ct <= ct1; ct++) {
        const int buf = (ct - ct0) & 1;
        if (ct < ct1) {
            at_load(sbase, b, (ct + 1) * 64, buf ^ 1);
            CP_COMMIT();
            CP_WAIT1();
        } else {
            CP_WAIT0();
        }
        __syncthreads();

        const uint32_t tb = sbase + (AT_TB + buf * AT_TBSZ) * 2;
        const int j0 = ct * 64;

        // ---- S = Q K^T ----
        float sacc[8][4];
        #pragma unroll
        for (int nt = 0; nt < 8; nt++)
            #pragma unroll
            for (int e = 0; e < 4; e++) sacc[nt][e] = 0.f;
        #pragma unroll
        for (int ks = 0; ks < 4; ks++) {
            const int kc = ks * 16;
            uint32_t ah[4], al[4];
            const uint32_t aaddr = sbase
                + ((w * 16 + arow) * AST + kc + ahalf * 8) * 2;
            LDMX4(ah, aaddr + AT_QH * 2);
            LDMX4(al, aaddr + AT_QL * 2);
            #pragma unroll
            for (int nt16 = 0; nt16 < 4; nt16++) {
                uint32_t bh[4], bl[4];
                const uint32_t baddr = tb + ((nt16 * 16 + brow) * AST + kc + bk) * 2;
                LDMX4(bh, baddr);
                LDMX4(bl, baddr + 9216);
                mma16816(sacc[2 * nt16],     ah, bh[0], bh[1]);
                mma16816(sacc[2 * nt16 + 1], ah, bh[2], bh[3]);
                mma16816(sacc[2 * nt16],     ah, bl[0], bl[1]);
                mma16816(sacc[2 * nt16 + 1], ah, bl[2], bl[3]);
                mma16816(sacc[2 * nt16],     al, bh[0], bh[1]);
                mma16816(sacc[2 * nt16 + 1], al, bh[2], bh[3]);
            }
        }

        // ---- bias + exp (+ mask), accumulate l ----
        float e[8][4];
        const float b0v = sRel[0];
        if (ct <= 2 * rt - 2) {
            #pragma unroll
            for (int nt = 0; nt < 8; nt++)
                #pragma unroll
                for (int u = 0; u < 4; u++)
                    e[nt][u] = __expf(sacc[nt][u] * 0.125f + b0v);
        } else {
            const int ia = i0 + w * 16 + frow;
            #pragma unroll
            for (int nt = 0; nt < 8; nt++) {
                const int jb2 = j0 + nt * 8 + fcol;
                #pragma unroll
                for (int u = 0; u < 4; u++) {
                    const int j = jb2 + (u & 1);
                    const int i = ia + (u >> 1) * 8;
                    const int d = j - i;
                    e[nt][u] = (d <= 0)
                        ? __expf(sacc[nt][u] * 0.125f + sRel[(d < -8 ? -8 : d) + 8])
                        : 0.f;
                }
            }
        }
        #pragma unroll
        for (int nt = 0; nt < 8; nt++) {
            l0 += e[nt][0] + e[nt][1];
            l1 += e[nt][2] + e[nt][3];
        }

        // ---- P fragments (accumulator layout == A-operand layout) ----
        uint32_t pah[4][4], pal[4][4];
        #pragma unroll
        for (int t = 0; t < 4; t++) {
            split_pack(e[2 * t][0],     e[2 * t][1],     pah[t][0], pal[t][0]);
            split_pack(e[2 * t][2],     e[2 * t][3],     pah[t][1], pal[t][1]);
            split_pack(e[2 * t + 1][0], e[2 * t + 1][1], pah[t][2], pal[t][2]);
            split_pack(e[2 * t + 1][2], e[2 * t + 1][3], pah[t][3], pal[t][3]);
        }

        // ---- O += P V (V natural layout, trans ldmatrix) ----
        #pragma unroll
        for (int js = 0; js < 4; js++) {
            const int jc = js * 16;
            #pragma unroll
            for (int h16 = 0; h16 < 4; h16++) {
                uint32_t vh4[4], vl4[4];
                const uint32_t vaddr = tb
                    + ((jc + vrow) * AST + h16 * 16 + vcol) * 2;
                LDMX4T(vh4, vaddr + 18432);
                LDMX4T(vl4, vaddr + 27648);
                mma16816(oacc[2 * h16],     pah[js], vh4[0], vh4[1]);
                mma16816(oacc[2 * h16 + 1], pah[js], vh4[2], vh4[3]);
                mma16816(oacc[2 * h16],     pah[js], vl4[0], vl4[1]);
                mma16816(oacc[2 * h16 + 1], pah[js], vl4[2], vl4[3]);
                mma16816(oacc[2 * h16],     pal[js], vh4[0], vh4[1]);
                mma16816(oacc[2 * h16 + 1], pal[js], vh4[2], vh4[3]);
            }
        }
        __syncthreads();
    }

    // reduce l within quads (lanes sharing rows)
    l0 += __shfl_xor_sync(0xffffffffu, l0, 1);
    l0 += __shfl_xor_sync(0xffffffffu, l0, 2);
    l1 += __shfl_xor_sync(0xffffffffu, l1, 1);
    l1 += __shfl_xor_sync(0xffffffffu, l1, 2);

    // write partials
    const size_t unit = ((size_t)(b * 32 + rt) * 8 + chunk);
    float* po = g_po + unit * 128 * 64;
    const int row = w * 16 + frow;
    #pragma unroll
    for (int nt = 0; nt < 8; nt++) {
        const int col = nt * 8 + fcol;
        *(float2*)(po + (size_t)row * 64 + col) =
            make_float2(oacc[nt][0], oacc[nt][1]);
        *(float2*)(po + (size_t)(row + 8) * 64 + col) =
            make_float2(oacc[nt][2], oacc[nt][3]);
    }
    if ((lane & 3) == 0) {
        g_pl[unit * 128 + row] = l0;
        g_pl[unit * 128 + row + 8] = l1;
    }
}

// ---------------------------------------------------------------------------
// Combine partials: out = (sum_p O_p) / (sum_p l_p).  Block = (rt, b).
// ---------------------------------------------------------------------------
__global__ void __launch_bounds__(256) combine_kernel(float* __restrict__ out)
{
    const int rt  = blockIdx.x;
    const int b   = blockIdx.y;
    const int nch = (2 * rt + 9) >> 3;
    const size_t base = (size_t)(b * 32 + rt) * 8;

    __shared__ float sInvL[128];

    const int tid = threadIdx.x;
    if (tid < 128) {
        float L = 0.f;
        for (int p = 0; p < nch; p++)
            L += g_pl[(base + p) * 128 + tid];
        sInvL[tid] = 1.0f / L;
    }
    __syncthreads();

    const int r  = tid >> 1;
    const int h0 = (tid & 1) * 32;
    float acc[32] = {};
    for (int p = 0; p < nch; p++) {
        const float* po = g_po + ((base + p) * 128 + r) * 64 + h0;
        #pragma unroll
        for (int u = 0; u < 32; u += 4) {
            float4 v = *(const float4*)(po + u);
            acc[u + 0] += v.x; acc[u + 1] += v.y;
            acc[u + 2] += v.z; acc[u + 3] += v.w;
        }
    }
    const float inv = sInvL[r];
    float* op = out + (size_t)(b * TT + rt * 128 + r) * DH + h0;
    #pragma unroll
    for (int u = 0; u < 32; u += 4)
        *(float4*)(op + u) = make_float4(acc[u] * inv, acc[u + 1] * inv,
                                         acc[u + 2] * inv, acc[u + 3] * inv);
}

extern "C" void kernel_launch(void* const* d_in, const int* in_sizes, int n_in,
                              void* d_out, int out_size)
{
    const float* x   = (const float*)d_in[0];
    const float* Wq  = (const float*)d_in[1];
    const float* Wk  = (const float*)d_in[2];
    const float* Wv  = (const float*)d_in[3];
    const float* rel = (const float*)d_in[4];
    float* out = (float*)d_out;

    dim3 wgrid(64, 3);
    convert_w_kernel<<<wgrid, 256>>>(Wq, Wk, Wv);

    cudaFuncSetAttribute(proj_mma_kernel,
                         cudaFuncAttributeMaxDynamicSharedMemorySize, PJ_SMEM);
    proj_mma_kernel<<<128, 256, PJ_SMEM>>>(x);

    cudaFuncSetAttribute(attn_mma_kernel,
                         cudaFuncAttributeMaxDynamicSharedMemorySize, AT_SMEM);
    dim3 agrid(32, 8, BB);
    attn_mma_kernel<<<agrid, 256, AT_SMEM>>>(rel);

    dim3 cgrid(32, BB);
    combine_kernel<<<cgrid, 256>>>(out);
}